// round 13
// baseline (speedup 1.0000x reference)
#include <cuda_runtime.h>
#include <cuda_bf16.h>
#include <math.h>
#include <cstdint>

#define BB 32
#define SS 2048
#define FF 128
#define DK 32
#define NROWS (BB*SS)
#define NSPLIT 8

// Packed projections, 64 bf16 per row (128B): [hi(32) | lo(32)]
// q pre-scaled by log2(e)/sqrt(32)  (scores in log2 domain -> ex2)
__device__ __nv_bfloat16 g_qp[NROWS*64];
__device__ __nv_bfloat16 g_kp[NROWS*64];
// PV B-operand, pre-packed bf16x2: per key-pair p, 8 cols g:
//   g<3: {lo=vw[2p][g], hi=vw[2p+1][g]}, g==3: {1,1}, g>3: 0
__device__ uint32_t g_vwp[(NROWS/2)*8];
__device__ float4 g_part[NSPLIT*NROWS];    // split-K partials {l, A0, A1, A2}
// Pre-split W images (ldmatrix-ready): per phase 8704 bf16 = 4352 hi + 4352 lo,
// layout img[c*136 + f] (c = out col 0..31, f = 0..127, 8 pad per row)
__device__ __nv_bfloat16 g_wimg[2][8704];
__device__ float g_wveff[FF*3];            // Wv @ Wo_eff
__device__ float g_cst[3];                 // bo + bv . Wo_eff

static __device__ __forceinline__ uint32_t smem_u32(const void* p) {
    uint32_t a;
    asm("{ .reg .u64 t; cvta.to.shared.u64 t, %1; cvt.u32.u64 %0, t; }" : "=r"(a) : "l"(p));
    return a;
}
static __device__ __forceinline__ void cp16(uint32_t dst, const void* src) {
    asm volatile("cp.async.cg.shared.global [%0], [%1], 16;" :: "r"(dst), "l"(src) : "memory");
}
#define CP_COMMIT() asm volatile("cp.async.commit_group;" ::: "memory")
#define CP_WAIT(n)  asm volatile("cp.async.wait_group %0;" :: "n"(n) : "memory")

static __device__ __forceinline__ float ex2f(float x) {
    float y; asm("ex2.approx.f32 %0, %1;" : "=f"(y) : "f"(x)); return y;
}
// pack {lo, hi} floats -> bf16x2 (memory order: lo first)
static __device__ __forceinline__ uint32_t pkbf(float lo, float hi) {
    uint32_t r;
    asm("cvt.rn.bf16x2.f32 %0, %1, %2;" : "=r"(r) : "f"(hi), "f"(lo));
    return r;
}
// split a float2 into bf16x2 hi + bf16x2 lo words
static __device__ __forceinline__ void split2(float2 x, uint32_t& h, uint32_t& l) {
    h = pkbf(x.x, x.y);
    float f0 = __uint_as_float(h << 16);
    float f1 = __uint_as_float(h & 0xFFFF0000u);
    l = pkbf(x.x - f0, x.y - f1);
}

#define LDSM_X4(r0,r1,r2,r3,addr) \
    asm volatile("ldmatrix.sync.aligned.m8n8.x4.shared.b16 {%0,%1,%2,%3}, [%4];" \
        : "=r"(r0), "=r"(r1), "=r"(r2), "=r"(r3) : "r"(addr))

#define MMA16816(c0,c1,c2,c3,a0,a1,a2,a3,b0,b1) \
    asm volatile("mma.sync.aligned.m16n8k16.row.col.f32.bf16.bf16.f32 " \
        "{%0,%1,%2,%3}, {%4,%5,%6,%7}, {%8,%9}, {%0,%1,%2,%3};" \
        : "+f"(c0), "+f"(c1), "+f"(c2), "+f"(c3) \
        : "r"(a0), "r"(a1), "r"(a2), "r"(a3), "r"(b0), "r"(b1))

// ---------------------------------------------------------------------------
// Prep: split/transposed W images + Wv_eff + output constant (runs once).
// ---------------------------------------------------------------------------
__global__ __launch_bounds__(256) void prep_kernel(
    const float* __restrict__ Wq, const float* __restrict__ Wk,
    const float* __restrict__ Wv, const float* __restrict__ Wo,
    const float* __restrict__ bv, const float* __restrict__ bo) {
    __shared__ float sWoE[DK*3];
    const int tid = threadIdx.x;
    #pragma unroll
    for (int p = 0; p < 2; ++p) {
        const float* W = p ? Wk : Wq;
        __nv_bfloat16* img = g_wimg[p];
        int c = tid & 31, fg = tid >> 5;
        #pragma unroll
        for (int i = 0; i < 16; ++i) {
            int f = fg*16 + i;
            float w = W[f*32 + c];
            __nv_bfloat16 h = __float2bfloat16(w);
            img[c*136 + f]        = h;
            img[4352 + c*136 + f] = __float2bfloat16(w - __bfloat162float(h));
        }
    }
    if (tid < 96) {
        int d = tid / 3, f = tid - d*3;
        float s = 0.f;
        #pragma unroll
        for (int h = 0; h < 16; ++h) s += Wo[(h*DK + d)*3 + f];
        sWoE[tid] = s;
    }
    __syncthreads();
    for (int i = tid; i < FF*3; i += 256) {
        int r = i / 3, f = i - r*3;
        float s = 0.f;
        #pragma unroll
        for (int d = 0; d < DK; ++d) s = fmaf(Wv[r*DK + d], sWoE[d*3 + f], s);
        g_wveff[i] = s;
    }
    if (tid < 3) {
        float s = bo[tid];
        #pragma unroll
        for (int d = 0; d < DK; ++d) s = fmaf(bv[d], sWoE[d*3 + tid], s);
        g_cst[tid] = s;
    }
}

// ---------------------------------------------------------------------------
// Projection: grid (512, 3), 256 threads, 128 rows/block.
// Q/K: A built in registers from global INSIDE the k-group loop (low reg
// pressure -> 4 blocks/SM); B from the pre-split W image. 3-term bf16 split.
// V: 4 threads/row + quad reduce, emits packed g_vwp fragments.
// ---------------------------------------------------------------------------
#define P6_SMEM 17536

__global__ __launch_bounds__(256, 4) void proj6_kernel(
    const float* __restrict__ qin, const float* __restrict__ kin, const float* __restrict__ vin,
    const float* __restrict__ bq, const float* __restrict__ bk) {
    extern __shared__ __align__(16) unsigned char dsm[];
    const int tid  = threadIdx.x;
    const int wid  = tid >> 5, lane = tid & 31;
    const int phase = blockIdx.y;
    const size_t row0 = (size_t)blockIdx.x * 128;
    const uint32_t sb = smem_u32(dsm);

    if (phase < 2) {
        const float* in = phase ? kin : qin;
        const float* bb = phase ? bk : bq;
        __nv_bfloat16* gout = phase ? g_kp : g_qp;
        const float qs = phase ? 1.0f
                               : 0.17677669529663687f * 1.4426950408889634f;

        // stage pre-split W image (17408 B)
        for (int i = tid; i < 1088; i += 256)
            cp16(sb + i*16, (const unsigned char*)g_wimg[phase] + i*16);
        CP_COMMIT();
        CP_WAIT(0);
        __syncthreads();

        const int gq = lane >> 2, tq = lane & 3;
        const int lr = lane & 7, sel = lane >> 3;
        const float* rp0 = in + (row0 + wid*16 + gq)*128;
        const float* rp1 = rp0 + 8*128;

        float acc[4][4];
        #pragma unroll
        for (int nt = 0; nt < 4; ++nt)
            #pragma unroll
            for (int i = 0; i < 4; ++i) acc[nt][i] = 0.f;

        #pragma unroll
        for (int g2 = 0; g2 < 4; ++g2) {
            // A for k-groups 2*g2, 2*g2+1 (just-in-time, 16 live regs)
            uint32_t ah[2][4], al[2][4];
            #pragma unroll
            for (int gg = 0; gg < 2; ++gg) {
                int cb = (2*g2 + gg)*16 + tq*2;
                float2 x00 = *(const float2*)(rp0 + cb);
                float2 x10 = *(const float2*)(rp1 + cb);
                float2 x01 = *(const float2*)(rp0 + cb + 8);
                float2 x11 = *(const float2*)(rp1 + cb + 8);
                split2(x00, ah[gg][0], al[gg][0]);
                split2(x10, ah[gg][1], al[gg][1]);
                split2(x01, ah[gg][2], al[gg][2]);
                split2(x11, ah[gg][3], al[gg][3]);
            }
            #pragma unroll
            for (int nt = 0; nt < 4; ++nt) {
                uint32_t bwh = sb + (nt*8 + lr)*272 + sel*16 + g2*64;
                uint32_t bwl = bwh + 8704;
                uint32_t bh[4], bl[4];
                LDSM_X4(bh[0], bh[1], bh[2], bh[3], bwh);
                LDSM_X4(bl[0], bl[1], bl[2], bl[3], bwl);
                MMA16816(acc[nt][0],acc[nt][1],acc[nt][2],acc[nt][3],
                         ah[0][0],ah[0][1],ah[0][2],ah[0][3], bh[0],bh[1]); // xh.wh
                MMA16816(acc[nt][0],acc[nt][1],acc[nt][2],acc[nt][3],
                         ah[1][0],ah[1][1],ah[1][2],ah[1][3], bh[2],bh[3]);
                MMA16816(acc[nt][0],acc[nt][1],acc[nt][2],acc[nt][3],
                         ah[0][0],ah[0][1],ah[0][2],ah[0][3], bl[0],bl[1]); // xh.wl
                MMA16816(acc[nt][0],acc[nt][1],acc[nt][2],acc[nt][3],
                         ah[1][0],ah[1][1],ah[1][2],ah[1][3], bl[2],bl[3]);
                MMA16816(acc[nt][0],acc[nt][1],acc[nt][2],acc[nt][3],
                         al[0][0],al[0][1],al[0][2],al[0][3], bh[0],bh[1]); // xl.wh
                MMA16816(acc[nt][0],acc[nt][1],acc[nt][2],acc[nt][3],
                         al[1][0],al[1][1],al[1][2],al[1][3], bh[2],bh[3]);
            }
        }

        // epilogue: bias + scale, split hi/lo, packed u32 stores
        #pragma unroll
        for (int nt = 0; nt < 4; ++nt) {
            int colp = nt*8 + tq*2;
            float b0 = bb[colp], b1 = bb[colp+1];
            #pragma unroll
            for (int hf = 0; hf < 2; ++hf) {
                size_t rrow = row0 + wid*16 + gq + hf*8;
                float v0 = (acc[nt][hf*2+0] + b0) * qs;
                float v1 = (acc[nt][hf*2+1] + b1) * qs;
                uint32_t hp = pkbf(v0, v1);
                float h0 = __uint_as_float(hp << 16);
                float h1 = __uint_as_float(hp & 0xFFFF0000u);
                uint32_t lp = pkbf(v0 - h0, v1 - h1);
                *(uint32_t*)((unsigned char*)gout + rrow*128 + colp*2)      = hp;
                *(uint32_t*)((unsigned char*)gout + rrow*128 + 64 + colp*2) = lp;
            }
        }
    } else {
        // V: vw rows via 4 threads/row + quad reduce, then pack fragments
        float* sWv = (float*)dsm;                 // [384]
        float* sVS = (float*)(dsm + 1536);        // [128][4]
        for (int i = tid; i < 384; i += 256) sWv[i] = g_wveff[i];
        __syncthreads();
        #pragma unroll
        for (int it = 0; it < 2; ++it) {
            int r = it*64 + (tid >> 2);
            const float* rp = vin + (row0 + r)*128 + (tid & 3)*32;
            float a0 = 0.f, a1 = 0.f, a2 = 0.f;
            #pragma unroll
            for (int f4 = 0; f4 < 8; ++f4) {
                float4 x = ((const float4*)rp)[f4];
                int f = (tid & 3)*32 + f4*4;
                a0 = fmaf(x.x, sWv[(f+0)*3+0], a0); a1 = fmaf(x.x, sWv[(f+0)*3+1], a1); a2 = fmaf(x.x, sWv[(f+0)*3+2], a2);
                a0 = fmaf(x.y, sWv[(f+1)*3+0], a0); a1 = fmaf(x.y, sWv[(f+1)*3+1], a1); a2 = fmaf(x.y, sWv[(f+1)*3+2], a2);
                a0 = fmaf(x.z, sWv[(f+2)*3+0], a0); a1 = fmaf(x.z, sWv[(f+2)*3+1], a1); a2 = fmaf(x.z, sWv[(f+2)*3+2], a2);
                a0 = fmaf(x.w, sWv[(f+3)*3+0], a0); a1 = fmaf(x.w, sWv[(f+3)*3+1], a1); a2 = fmaf(x.w, sWv[(f+3)*3+2], a2);
            }
            a0 += __shfl_xor_sync(0xffffffffu, a0, 1); a0 += __shfl_xor_sync(0xffffffffu, a0, 2);
            a1 += __shfl_xor_sync(0xffffffffu, a1, 1); a1 += __shfl_xor_sync(0xffffffffu, a1, 2);
            a2 += __shfl_xor_sync(0xffffffffu, a2, 1); a2 += __shfl_xor_sync(0xffffffffu, a2, 2);
            if ((tid & 3) == 0) {
                sVS[r*4 + 0] = a0; sVS[r*4 + 1] = a1; sVS[r*4 + 2] = a2;
            }
        }
        __syncthreads();
        for (int i = tid; i < 512; i += 256) {
            int p = i >> 3, g = i & 7;
            uint32_t w;
            if (g < 3)       w = pkbf(sVS[(2*p)*4 + g], sVS[(2*p+1)*4 + g]);
            else if (g == 3) w = 0x3F803F80u;       // {1.0bf, 1.0bf}
            else             w = 0u;
            g_vwp[(row0 >> 1)*8 + i] = w;
        }
    }
}

// ---------------------------------------------------------------------------
// Flash kernel: 256 threads (8 warps x 32 q-rows), q-tile 256, split-K 8
// (2 K-tiles = 256 keys per block). Q staged in the ring smem (A-frags
// extracted to regs before overwrite); smem 40960 B. QK^T bf16-split HMMA;
// ex2 softmax (no max); PV via HMMA with pre-packed vwp fragments.
// ---------------------------------------------------------------------------
#define RSTRK 144
#define KTILEB (128*RSTRK)                 // 18432
#define RINGSTRIDE (KTILEB + 2048)         // 20480 (K tile + vwp)
#define SMEM_BYTES (2*RINGSTRIDE)          // 40960

__global__ __launch_bounds__(256, 3)
void flash10_kernel(void) {
    extern __shared__ __align__(16) unsigned char smem[];
    const int tid  = threadIdx.x;
    const int wid  = tid >> 5, lane = tid & 31;
    const size_t base = (size_t)blockIdx.y * SS;
    const int q0 = blockIdx.x * 256;
    const int z  = blockIdx.z;             // 0..7, keys [z*256, z*256+256)
    const uint32_t sbase = smem_u32(smem);

    // stage Q tile (256 rows x 128B = 32 KB) across the ring area
    #pragma unroll
    for (int k = 0; k < 8; ++k) {
        int i = tid + k*256;
        cp16(sbase + i*16, (const unsigned char*)g_qp + (base + q0)*128 + i*16);
    }
    CP_COMMIT();
    CP_WAIT(0);
    __syncthreads();

    const int lr  = lane & 7;
    const int sel = lane >> 3;

    // A fragments (loop-invariant): per m-tile, qh steps {0,1}, ql steps {0,1}
    uint32_t aF[2][4][4];
    #pragma unroll
    for (int mt = 0; mt < 2; ++mt) {
        int arow = wid*32 + mt*16 + lr + (sel & 1)*8;
        uint32_t abase = sbase + arow*128 + (sel >> 1)*16;
        #pragma unroll
        for (int g = 0; g < 4; ++g)
            LDSM_X4(aF[mt][g][0], aF[mt][g][1], aF[mt][g][2], aF[mt][g][3], abase + g*32);
    }
    __syncthreads();   // all warps done reading Q region

    // prefetch K tile 0 + vwp into ring buffer 0 (overwrites Q staging)
    {
        const size_t kb = base + (size_t)z * 256;
        #pragma unroll
        for (int k = 0; k < 4; ++k) {
            int i = tid + k*256;
            int rr = i >> 3, sg = i & 7;
            cp16(sbase + rr*RSTRK + sg*16,
                 (const unsigned char*)g_kp + (kb + rr)*128 + sg*16);
        }
        if (tid < 128)
            cp16(sbase + KTILEB + tid*16, g_vwp + (kb >> 1)*8 + tid*4);
    }
    CP_COMMIT();

    // PV accumulators: cols 2t,2t+1 (t=lane&3): t=0 -> {A0,A1}, t=1 -> {A2,l}
    float d[2][4];
    #pragma unroll
    for (int mt = 0; mt < 2; ++mt)
        #pragma unroll
        for (int i = 0; i < 4; ++i) d[mt][i] = 0.f;
    const int tq = lane & 3, gq = lane >> 2;

    #pragma unroll 1
    for (int ti = 0; ti < 2; ++ti) {
        if (ti < 1) {
            const size_t kb = base + (size_t)z*256 + 128;
            uint32_t db = sbase + RINGSTRIDE;
            #pragma unroll
            for (int k = 0; k < 4; ++k) {
                int i = tid + k*256;
                int rr = i >> 3, sg = i & 7;
                cp16(db + rr*RSTRK + sg*16,
                     (const unsigned char*)g_kp + (kb + rr)*128 + sg*16);
            }
            if (tid < 128)
                cp16(db + KTILEB + tid*16, g_vwp + (kb >> 1)*8 + tid*4);
            CP_COMMIT();
            CP_WAIT(1);
        } else {
            CP_WAIT(0);
        }
        __syncthreads();

        const uint32_t sk  = sbase + ti*RINGSTRIDE;
        const uint32_t svw = sk + KTILEB;

        #pragma unroll 2
        for (int jp = 0; jp < 8; ++jp) {
            uint32_t be[8], bo_[8];
            {
                uint32_t bb = sk + ((2*jp)*8 + lr)*RSTRK + sel*16;
                LDSM_X4(be[0], be[1], be[2], be[3], bb);
                LDSM_X4(be[4], be[5], be[6], be[7], bb + 64);
                uint32_t bb2 = sk + ((2*jp+1)*8 + lr)*RSTRK + sel*16;
                LDSM_X4(bo_[0], bo_[1], bo_[2], bo_[3], bb2);
                LDSM_X4(bo_[4], bo_[5], bo_[6], bo_[7], bb2 + 64);
            }
            uint32_t pb0, pb1;
            asm volatile("ld.shared.b32 %0, [%1];" : "=r"(pb0)
                         : "r"(svw + ((jp*8 + tq)*8 + gq)*4));
            asm volatile("ld.shared.b32 %0, [%1];" : "=r"(pb1)
                         : "r"(svw + ((jp*8 + 4 + tq)*8 + gq)*4));

            #pragma unroll
            for (int mt = 0; mt < 2; ++mt) {
                float e0=0.f,e1=0.f,e2=0.f,e3=0.f;   // j even scores
                float o0=0.f,o1=0.f,o2=0.f,o3=0.f;   // j odd scores
                MMA16816(e0,e1,e2,e3, aF[mt][0][0],aF[mt][0][1],aF[mt][0][2],aF[mt][0][3], be[0],be[1]);
                MMA16816(o0,o1,o2,o3, aF[mt][0][0],aF[mt][0][1],aF[mt][0][2],aF[mt][0][3], bo_[0],bo_[1]);
                MMA16816(e0,e1,e2,e3, aF[mt][1][0],aF[mt][1][1],aF[mt][1][2],aF[mt][1][3], be[2],be[3]);
                MMA16816(o0,o1,o2,o3, aF[mt][1][0],aF[mt][1][1],aF[mt][1][2],aF[mt][1][3], bo_[2],bo_[3]);
                MMA16816(e0,e1,e2,e3, aF[mt][0][0],aF[mt][0][1],aF[mt][0][2],aF[mt][0][3], be[4],be[5]);
                MMA16816(o0,o1,o2,o3, aF[mt][0][0],aF[mt][0][1],aF[mt][0][2],aF[mt][0][3], bo_[4],bo_[5]);
                MMA16816(e0,e1,e2,e3, aF[mt][1][0],aF[mt][1][1],aF[mt][1][2],aF[mt][1][3], be[6],be[7]);
                MMA16816(o0,o1,o2,o3, aF[mt][1][0],aF[mt][1][1],aF[mt][1][2],aF[mt][1][3], bo_[6],bo_[7]);
                MMA16816(e0,e1,e2,e3, aF[mt][2][0],aF[mt][2][1],aF[mt][2][2],aF[mt][2][3], be[0],be[1]);
                MMA16816(o0,o1,o2,o3, aF[mt][2][0],aF[mt][2][1],aF[mt][2][2],aF[mt][2][3], bo_[0],bo_[1]);
                MMA16816(e0,e1,e2,e3, aF[mt][3][0],aF[mt][3][1],aF[mt][3][2],aF[mt][3][3], be[2],be[3]);
                MMA16816(o0,o1,o2,o3, aF[mt][3][0],aF[mt][3][1],aF[mt][3][2],aF[mt][3][3], bo_[2],bo_[3]);

                float p0 = ex2f(e0), p1 = ex2f(e1), p2 = ex2f(e2), p3 = ex2f(e3);
                float p4 = ex2f(o0), p5 = ex2f(o1), p6 = ex2f(o2), p7 = ex2f(o3);
                uint32_t a0 = pkbf(p0, p1);
                uint32_t a1 = pkbf(p2, p3);
                uint32_t a2 = pkbf(p4, p5);
                uint32_t a3 = pkbf(p6, p7);
                MMA16816(d[mt][0], d[mt][1], d[mt][2], d[mt][3],
                         a0, a1, a2, a3, pb0, pb1);
            }
        }
        __syncthreads();
    }

    // gather: t=0 lanes hold {A0,A1}; t=1 lanes hold {A2,l}; shuffle-combine
    #pragma unroll
    for (int mt = 0; mt < 2; ++mt) {
        float az_r0 = __shfl_xor_sync(0xffffffffu, d[mt][0], 1);  // from t^1
        float l_r0  = __shfl_xor_sync(0xffffffffu, d[mt][1], 1);
        float az_r1 = __shfl_xor_sync(0xffffffffu, d[mt][2], 1);
        float l_r1  = __shfl_xor_sync(0xffffffffu, d[mt][3], 1);
        if (tq == 0) {
            size_t r = base + q0 + wid*32 + mt*16 + gq;
            g_part[(size_t)z*NROWS + r]     = make_float4(l_r0, d[mt][0], d[mt][1], az_r0);
            g_part[(size_t)z*NROWS + r + 8] = make_float4(l_r1, d[mt][2], d[mt][3], az_r1);
        }
    }
}

// ---------------------------------------------------------------------------
// Finalize: combine 8 split-K partials, normalize, add precomputed constant.
// ---------------------------------------------------------------------------
__global__ __launch_bounds__(256) void finalize_kernel(float* __restrict__ out) {
    const int tid = threadIdx.x;
    const float c0 = g_cst[0], c1 = g_cst[1], c2 = g_cst[2];
    size_t row = (size_t)blockIdx.x * 256 + tid;
    float l = 0.f, a0 = 0.f, a1 = 0.f, a2 = 0.f;
    #pragma unroll
    for (int zz = 0; zz < NSPLIT; ++zz) {
        float4 p = g_part[(size_t)zz*NROWS + row];
        l += p.x; a0 += p.y; a1 += p.z; a2 += p.w;
    }
    float inv = 1.0f / l;
    out[row*3 + 0] = fmaf(a0, inv, c0);
    out[row*3 + 1] = fmaf(a1, inv, c1);
    out[row*3 + 2] = fmaf(a2, inv, c2);
}

extern "C" void kernel_launch(void* const* d_in, const int* in_sizes, int n_in,
                              void* d_out, int out_size) {
    const float* qin = (const float*)d_in[0];
    const float* kin = (const float*)d_in[1];
    const float* vin = (const float*)d_in[2];
    const float* Wq  = (const float*)d_in[3];
    const float* bq  = (const float*)d_in[4];
    const float* Wk  = (const float*)d_in[5];
    const float* bk  = (const float*)d_in[6];
    const float* Wv  = (const float*)d_in[7];
    const float* bv  = (const float*)d_in[8];
    const float* Wo  = (const float*)d_in[9];
    const float* bo  = (const float*)d_in[10];
    float* out = (float*)d_out;

    cudaFuncSetAttribute(flash10_kernel,
                         cudaFuncAttributeMaxDynamicSharedMemorySize, SMEM_BYTES);
    cudaFuncSetAttribute(proj6_kernel,
                         cudaFuncAttributeMaxDynamicSharedMemorySize, P6_SMEM);
    prep_kernel<<<1, 256>>>(Wq, Wk, Wv, Wo, bv, bo);
    proj6_kernel<<<dim3(NROWS/128, 3), 256, P6_SMEM>>>(qin, kin, vin, bq, bk);
    flash10_kernel<<<dim3(SS/256, BB, NSPLIT), 256, SMEM_BYTES>>>();
    finalize_kernel<<<NROWS/256, 256>>>(out);
}

// round 14
// speedup vs baseline: 1.0647x; 1.0647x over previous
#include <cuda_runtime.h>
#include <cuda_bf16.h>
#include <math.h>
#include <cstdint>

#define BB 32
#define SS 2048
#define FF 128
#define DK 32
#define NROWS (BB*SS)

// Packed projections, 64 bf16 per row (128B): [hi(32) | lo(32)]
// q pre-scaled by log2(e)/sqrt(32)  (scores in log2 domain -> ex2)
__device__ __nv_bfloat16 g_qp[NROWS*64];
__device__ __nv_bfloat16 g_kp[NROWS*64];
// PV B-operand, pre-packed fp16x2: per key-pair p, 8 cols g:
//   g<3: {lo=vw[2p][g], hi=vw[2p+1][g]}, g==3: {1,1}, g>3: 0
__device__ uint32_t g_vwp[(NROWS/2)*8];
__device__ float4 g_part[2*NROWS];         // split-K partials {l, A0, A1, A2}
// Pre-split W images (ldmatrix-ready): per phase 8704 bf16 = 4352 hi + 4352 lo,
// layout img[c*136 + f] (c = out col 0..31, f = 0..127, 8 pad per row)
__device__ __nv_bfloat16 g_wimg[2][8704];
__device__ float g_wveff[FF*3];            // Wv @ Wo_eff
__device__ float g_cst[3];                 // bo + bv . Wo_eff

static __device__ __forceinline__ uint32_t smem_u32(const void* p) {
    uint32_t a;
    asm("{ .reg .u64 t; cvta.to.shared.u64 t, %1; cvt.u32.u64 %0, t; }" : "=r"(a) : "l"(p));
    return a;
}
static __device__ __forceinline__ void cp16(uint32_t dst, const void* src) {
    asm volatile("cp.async.cg.shared.global [%0], [%1], 16;" :: "r"(dst), "l"(src) : "memory");
}
#define CP_COMMIT() asm volatile("cp.async.commit_group;" ::: "memory")
#define CP_WAIT(n)  asm volatile("cp.async.wait_group %0;" :: "n"(n) : "memory")

// pack {lo, hi} floats -> bf16x2
static __device__ __forceinline__ uint32_t pkbf(float lo, float hi) {
    uint32_t r;
    asm("cvt.rn.bf16x2.f32 %0, %1, %2;" : "=r"(r) : "f"(hi), "f"(lo));
    return r;
}
// pack {lo, hi} floats -> f16x2
static __device__ __forceinline__ uint32_t pkhf(float lo, float hi) {
    uint32_t r;
    asm("cvt.rn.f16x2.f32 %0, %1, %2;" : "=r"(r) : "f"(hi), "f"(lo));
    return r;
}
// packed fp16x2 exp2
static __device__ __forceinline__ uint32_t ex2h2(uint32_t x) {
    uint32_t y;
    asm("ex2.approx.f16x2 %0, %1;" : "=r"(y) : "r"(x));
    return y;
}
// split a float2 into bf16x2 hi + bf16x2 lo words
static __device__ __forceinline__ void split2(float2 x, uint32_t& h, uint32_t& l) {
    h = pkbf(x.x, x.y);
    float f0 = __uint_as_float(h << 16);
    float f1 = __uint_as_float(h & 0xFFFF0000u);
    l = pkbf(x.x - f0, x.y - f1);
}

#define LDSM_X4(r0,r1,r2,r3,addr) \
    asm volatile("ldmatrix.sync.aligned.m8n8.x4.shared.b16 {%0,%1,%2,%3}, [%4];" \
        : "=r"(r0), "=r"(r1), "=r"(r2), "=r"(r3) : "r"(addr))

#define MMA16816(c0,c1,c2,c3,a0,a1,a2,a3,b0,b1) \
    asm volatile("mma.sync.aligned.m16n8k16.row.col.f32.bf16.bf16.f32 " \
        "{%0,%1,%2,%3}, {%4,%5,%6,%7}, {%8,%9}, {%0,%1,%2,%3};" \
        : "+f"(c0), "+f"(c1), "+f"(c2), "+f"(c3) \
        : "r"(a0), "r"(a1), "r"(a2), "r"(a3), "r"(b0), "r"(b1))

#define MMA16816H(c0,c1,c2,c3,a0,a1,a2,a3,b0,b1) \
    asm volatile("mma.sync.aligned.m16n8k16.row.col.f32.f16.f16.f32 " \
        "{%0,%1,%2,%3}, {%4,%5,%6,%7}, {%8,%9}, {%0,%1,%2,%3};" \
        : "+f"(c0), "+f"(c1), "+f"(c2), "+f"(c3) \
        : "r"(a0), "r"(a1), "r"(a2), "r"(a3), "r"(b0), "r"(b1))

// ---------------------------------------------------------------------------
// Prep: split/transposed W images + Wv_eff + output constant (runs once).
// ---------------------------------------------------------------------------
__global__ __launch_bounds__(256) void prep_kernel(
    const float* __restrict__ Wq, const float* __restrict__ Wk,
    const float* __restrict__ Wv, const float* __restrict__ Wo,
    const float* __restrict__ bv, const float* __restrict__ bo) {
    __shared__ float sWoE[DK*3];
    const int tid = threadIdx.x;
    #pragma unroll
    for (int p = 0; p < 2; ++p) {
        const float* W = p ? Wk : Wq;
        __nv_bfloat16* img = g_wimg[p];
        int c = tid & 31, fg = tid >> 5;
        #pragma unroll
        for (int i = 0; i < 16; ++i) {
            int f = fg*16 + i;
            float w = W[f*32 + c];
            __nv_bfloat16 h = __float2bfloat16(w);
            img[c*136 + f]        = h;
            img[4352 + c*136 + f] = __float2bfloat16(w - __bfloat162float(h));
        }
    }
    if (tid < 96) {
        int d = tid / 3, f = tid - d*3;
        float s = 0.f;
        #pragma unroll
        for (int h = 0; h < 16; ++h) s += Wo[(h*DK + d)*3 + f];
        sWoE[tid] = s;
    }
    __syncthreads();
    for (int i = tid; i < FF*3; i += 256) {
        int r = i / 3, f = i - r*3;
        float s = 0.f;
        #pragma unroll
        for (int d = 0; d < DK; ++d) s = fmaf(Wv[r*DK + d], sWoE[d*3 + f], s);
        g_wveff[i] = s;
    }
    if (tid < 3) {
        float s = bo[tid];
        #pragma unroll
        for (int d = 0; d < DK; ++d) s = fmaf(bv[d], sWoE[d*3 + tid], s);
        g_cst[tid] = s;
    }
}

// ---------------------------------------------------------------------------
// Projection: grid (512, 3), 256 threads, 128 rows/block.
// Q/K: A built in registers from global INSIDE the k-group loop (low reg
// pressure -> 4 blocks/SM); B from the pre-split W image. 3-term bf16 split.
// V: 4 threads/row + quad reduce, emits packed fp16 g_vwp fragments.
// ---------------------------------------------------------------------------
#define P6_SMEM 17536

__global__ __launch_bounds__(256, 4) void proj6_kernel(
    const float* __restrict__ qin, const float* __restrict__ kin, const float* __restrict__ vin,
    const float* __restrict__ bq, const float* __restrict__ bk) {
    extern __shared__ __align__(16) unsigned char dsm[];
    const int tid  = threadIdx.x;
    const int wid  = tid >> 5, lane = tid & 31;
    const int phase = blockIdx.y;
    const size_t row0 = (size_t)blockIdx.x * 128;
    const uint32_t sb = smem_u32(dsm);

    if (phase < 2) {
        const float* in = phase ? kin : qin;
        const float* bb = phase ? bk : bq;
        __nv_bfloat16* gout = phase ? g_kp : g_qp;
        const float qs = phase ? 1.0f
                               : 0.17677669529663687f * 1.4426950408889634f;

        // stage pre-split W image (17408 B)
        for (int i = tid; i < 1088; i += 256)
            cp16(sb + i*16, (const unsigned char*)g_wimg[phase] + i*16);
        CP_COMMIT();
        CP_WAIT(0);
        __syncthreads();

        const int gq = lane >> 2, tq = lane & 3;
        const int lr = lane & 7, sel = lane >> 3;
        const float* rp0 = in + (row0 + wid*16 + gq)*128;
        const float* rp1 = rp0 + 8*128;

        float acc[4][4];
        #pragma unroll
        for (int nt = 0; nt < 4; ++nt)
            #pragma unroll
            for (int i = 0; i < 4; ++i) acc[nt][i] = 0.f;

        #pragma unroll
        for (int g2 = 0; g2 < 4; ++g2) {
            // A for k-groups 2*g2, 2*g2+1 (just-in-time, 16 live regs)
            uint32_t ah[2][4], al[2][4];
            #pragma unroll
            for (int gg = 0; gg < 2; ++gg) {
                int cb = (2*g2 + gg)*16 + tq*2;
                float2 x00 = *(const float2*)(rp0 + cb);
                float2 x10 = *(const float2*)(rp1 + cb);
                float2 x01 = *(const float2*)(rp0 + cb + 8);
                float2 x11 = *(const float2*)(rp1 + cb + 8);
                split2(x00, ah[gg][0], al[gg][0]);
                split2(x10, ah[gg][1], al[gg][1]);
                split2(x01, ah[gg][2], al[gg][2]);
                split2(x11, ah[gg][3], al[gg][3]);
            }
            #pragma unroll
            for (int nt = 0; nt < 4; ++nt) {
                uint32_t bwh = sb + (nt*8 + lr)*272 + sel*16 + g2*64;
                uint32_t bwl = bwh + 8704;
                uint32_t bh[4], bl[4];
                LDSM_X4(bh[0], bh[1], bh[2], bh[3], bwh);
                LDSM_X4(bl[0], bl[1], bl[2], bl[3], bwl);
                MMA16816(acc[nt][0],acc[nt][1],acc[nt][2],acc[nt][3],
                         ah[0][0],ah[0][1],ah[0][2],ah[0][3], bh[0],bh[1]); // xh.wh
                MMA16816(acc[nt][0],acc[nt][1],acc[nt][2],acc[nt][3],
                         ah[1][0],ah[1][1],ah[1][2],ah[1][3], bh[2],bh[3]);
                MMA16816(acc[nt][0],acc[nt][1],acc[nt][2],acc[nt][3],
                         ah[0][0],ah[0][1],ah[0][2],ah[0][3], bl[0],bl[1]); // xh.wl
                MMA16816(acc[nt][0],acc[nt][1],acc[nt][2],acc[nt][3],
                         ah[1][0],ah[1][1],ah[1][2],ah[1][3], bl[2],bl[3]);
                MMA16816(acc[nt][0],acc[nt][1],acc[nt][2],acc[nt][3],
                         al[0][0],al[0][1],al[0][2],al[0][3], bh[0],bh[1]); // xl.wh
                MMA16816(acc[nt][0],acc[nt][1],acc[nt][2],acc[nt][3],
                         al[1][0],al[1][1],al[1][2],al[1][3], bh[2],bh[3]);
            }
        }

        // epilogue: bias + scale, split hi/lo, packed u32 stores
        #pragma unroll
        for (int nt = 0; nt < 4; ++nt) {
            int colp = nt*8 + tq*2;
            float b0 = bb[colp], b1 = bb[colp+1];
            #pragma unroll
            for (int hf = 0; hf < 2; ++hf) {
                size_t rrow = row0 + wid*16 + gq + hf*8;
                float v0 = (acc[nt][hf*2+0] + b0) * qs;
                float v1 = (acc[nt][hf*2+1] + b1) * qs;
                uint32_t hp = pkbf(v0, v1);
                float h0 = __uint_as_float(hp << 16);
                float h1 = __uint_as_float(hp & 0xFFFF0000u);
                uint32_t lp = pkbf(v0 - h0, v1 - h1);
                *(uint32_t*)((unsigned char*)gout + rrow*128 + colp*2)      = hp;
                *(uint32_t*)((unsigned char*)gout + rrow*128 + 64 + colp*2) = lp;
            }
        }
    } else {
        // V: vw rows via 4 threads/row + quad reduce, then pack fp16 fragments
        float* sWv = (float*)dsm;                 // [384]
        float* sVS = (float*)(dsm + 1536);        // [128][4]
        for (int i = tid; i < 384; i += 256) sWv[i] = g_wveff[i];
        __syncthreads();
        #pragma unroll
        for (int it = 0; it < 2; ++it) {
            int r = it*64 + (tid >> 2);
            const float* rp = vin + (row0 + r)*128 + (tid & 3)*32;
            float a0 = 0.f, a1 = 0.f, a2 = 0.f;
            #pragma unroll
            for (int f4 = 0; f4 < 8; ++f4) {
                float4 x = ((const float4*)rp)[f4];
                int f = (tid & 3)*32 + f4*4;
                a0 = fmaf(x.x, sWv[(f+0)*3+0], a0); a1 = fmaf(x.x, sWv[(f+0)*3+1], a1); a2 = fmaf(x.x, sWv[(f+0)*3+2], a2);
                a0 = fmaf(x.y, sWv[(f+1)*3+0], a0); a1 = fmaf(x.y, sWv[(f+1)*3+1], a1); a2 = fmaf(x.y, sWv[(f+1)*3+2], a2);
                a0 = fmaf(x.z, sWv[(f+2)*3+0], a0); a1 = fmaf(x.z, sWv[(f+2)*3+1], a1); a2 = fmaf(x.z, sWv[(f+2)*3+2], a2);
                a0 = fmaf(x.w, sWv[(f+3)*3+0], a0); a1 = fmaf(x.w, sWv[(f+3)*3+1], a1); a2 = fmaf(x.w, sWv[(f+3)*3+2], a2);
            }
            a0 += __shfl_xor_sync(0xffffffffu, a0, 1); a0 += __shfl_xor_sync(0xffffffffu, a0, 2);
            a1 += __shfl_xor_sync(0xffffffffu, a1, 1); a1 += __shfl_xor_sync(0xffffffffu, a1, 2);
            a2 += __shfl_xor_sync(0xffffffffu, a2, 1); a2 += __shfl_xor_sync(0xffffffffu, a2, 2);
            if ((tid & 3) == 0) {
                sVS[r*4 + 0] = a0; sVS[r*4 + 1] = a1; sVS[r*4 + 2] = a2;
            }
        }
        __syncthreads();
        for (int i = tid; i < 512; i += 256) {
            int p = i >> 3, g = i & 7;
            uint32_t w;
            if (g < 3)       w = pkhf(sVS[(2*p)*4 + g], sVS[(2*p+1)*4 + g]);
            else if (g == 3) w = 0x3C003C00u;       // {1.0h, 1.0h}
            else             w = 0u;
            g_vwp[(row0 >> 1)*8 + i] = w;
        }
    }
}

// ---------------------------------------------------------------------------
// Flash kernel: 256 threads (8 warps x 16 q-rows), q-tile 128, split-K 2-way.
// Q staged in the K-ring smem; smem 40960 B -> 4 blocks/SM. QK^T bf16-split
// HMMA; softmax via packed ex2.f16x2 (scores pre-shifted by -18, cancels in
// normalization); PV via fp16 HMMA with pre-packed vwp fragments.
// ---------------------------------------------------------------------------
#define RSTRK 144
#define KTILEB (128*RSTRK)                 // 18432
#define RINGSTRIDE (KTILEB + 2048)         // 20480 (K tile + vwp)
#define SMEM_BYTES (2*RINGSTRIDE)          // 40960

__global__ __launch_bounds__(256, 4)
void flash11_kernel(void) {
    extern __shared__ __align__(16) unsigned char smem[];
    const int tid  = threadIdx.x;
    const int wid  = tid >> 5, lane = tid & 31;
    const size_t base = (size_t)blockIdx.y * SS;
    const int q0 = blockIdx.x * 128;
    const int z  = blockIdx.z;
    const uint32_t sbase = smem_u32(smem);

    // stage Q tile (128 rows x 128B = 16 KB) in the ring area
    #pragma unroll
    for (int k = 0; k < 4; ++k) {
        int i = tid + k*256;
        cp16(sbase + i*16, (const unsigned char*)g_qp + (base + q0)*128 + i*16);
    }
    CP_COMMIT();
    CP_WAIT(0);
    __syncthreads();

    const int lr  = lane & 7;
    const int sel = lane >> 3;

    // A fragments (loop-invariant): qh steps {0,1}, ql steps {0,1}
    uint32_t aF[4][4];
    {
        int arow = wid*16 + lr + (sel & 1)*8;
        uint32_t abase = sbase + arow*128 + (sel >> 1)*16;
        #pragma unroll
        for (int g = 0; g < 4; ++g)
            LDSM_X4(aF[g][0], aF[g][1], aF[g][2], aF[g][3], abase + g*32);
    }
    __syncthreads();   // all warps done reading Q region

    // prefetch K tile 0 + vwp into ring buffer 0 (overwrites Q staging)
    {
        const size_t kb = base + (size_t)z * 1024;
        #pragma unroll
        for (int k = 0; k < 4; ++k) {
            int i = tid + k*256;
            int rr = i >> 3, sg = i & 7;
            cp16(sbase + rr*RSTRK + sg*16,
                 (const unsigned char*)g_kp + (kb + rr)*128 + sg*16);
        }
        if (tid < 128)
            cp16(sbase + KTILEB + tid*16, g_vwp + (kb >> 1)*8 + tid*4);
    }
    CP_COMMIT();

    // PV accumulators: cols 2t,2t+1 (t=lane&3): t=0 -> {A0,A1}, t=1 -> {A2,l}
    float d[4] = {0.f, 0.f, 0.f, 0.f};
    const int tq = lane & 3, gq = lane >> 2;

    #pragma unroll 1
    for (int ti = 0; ti < 8; ++ti) {
        if (ti < 7) {
            const size_t kb = base + (size_t)z*1024 + (size_t)(ti+1)*128;
            uint32_t db = sbase + ((ti+1) & 1)*RINGSTRIDE;
            #pragma unroll
            for (int k = 0; k < 4; ++k) {
                int i = tid + k*256;
                int rr = i >> 3, sg = i & 7;
                cp16(db + rr*RSTRK + sg*16,
                     (const unsigned char*)g_kp + (kb + rr)*128 + sg*16);
            }
            if (tid < 128)
                cp16(db + KTILEB + tid*16, g_vwp + (kb >> 1)*8 + tid*4);
            CP_COMMIT();
            CP_WAIT(1);
        } else {
            CP_WAIT(0);
        }
        __syncthreads();

        const uint32_t sk  = sbase + (ti & 1)*RINGSTRIDE;
        const uint32_t svw = sk + KTILEB;

        #pragma unroll 2
        for (int jp = 0; jp < 8; ++jp) {
            uint32_t be[8], bo_[8];
            {
                uint32_t bb = sk + ((2*jp)*8 + lr)*RSTRK + sel*16;
                LDSM_X4(be[0], be[1], be[2], be[3], bb);
                LDSM_X4(be[4], be[5], be[6], be[7], bb + 64);
                uint32_t bb2 = sk + ((2*jp+1)*8 + lr)*RSTRK + sel*16;
                LDSM_X4(bo_[0], bo_[1], bo_[2], bo_[3], bb2);
                LDSM_X4(bo_[4], bo_[5], bo_[6], bo_[7], bb2 + 64);
            }
            uint32_t pb0, pb1;
            asm volatile("ld.shared.b32 %0, [%1];" : "=r"(pb0)
                         : "r"(svw + ((jp*8 + tq)*8 + gq)*4));
            asm volatile("ld.shared.b32 %0, [%1];" : "=r"(pb1)
                         : "r"(svw + ((jp*8 + 4 + tq)*8 + gq)*4));

            // e-chain pre-shifted by -18 (softmax shift-invariant; keeps
            // exp2 results inside fp16 range)
            float e0=-18.f,e1=-18.f,e2=-18.f,e3=-18.f;   // j even scores
            float o0=0.f,o1=0.f,o2=0.f,o3=0.f;           // j odd part
            MMA16816(e0,e1,e2,e3, aF[0][0],aF[0][1],aF[0][2],aF[0][3], be[0],be[1]);
            MMA16816(o0,o1,o2,o3, aF[0][0],aF[0][1],aF[0][2],aF[0][3], bo_[0],bo_[1]);
            MMA16816(e0,e1,e2,e3, aF[1][0],aF[1][1],aF[1][2],aF[1][3], be[2],be[3]);
            MMA16816(o0,o1,o2,o3, aF[1][0],aF[1][1],aF[1][2],aF[1][3], bo_[2],bo_[3]);
            MMA16816(e0,e1,e2,e3, aF[0][0],aF[0][1],aF[0][2],aF[0][3], be[4],be[5]);
            MMA16816(o0,o1,o2,o3, aF[0][0],aF[0][1],aF[0][2],aF[0][3], bo_[4],bo_[5]);
            MMA16816(e0,e1,e2,e3, aF[1][0],aF[1][1],aF[1][2],aF[1][3], be[6],be[7]);
            MMA16816(o0,o1,o2,o3, aF[1][0],aF[1][1],aF[1][2],aF[1][3], bo_[6],bo_[7]);
            MMA16816(e0,e1,e2,e3, aF[2][0],aF[2][1],aF[2][2],aF[2][3], be[0],be[1]);
            MMA16816(o0,o1,o2,o3, aF[2][0],aF[2][1],aF[2][2],aF[2][3], bo_[0],bo_[1]);
            MMA16816(e0,e1,e2,e3, aF[3][0],aF[3][1],aF[3][2],aF[3][3], be[2],be[3]);
            MMA16816(o0,o1,o2,o3, aF[3][0],aF[3][1],aF[3][2],aF[3][3], bo_[2],bo_[3]);

            // NOTE: odd-tile scores come from the o-chain MMAs on the odd
            // B fragments, summed with the e-chain's -18 shift via the
            // even/odd pairing below. o-chain carries the odd n-tile; the
            // -18 shift is applied once per score by pairing with e-init.
            // scores: even tile = e, odd tile = o - 18 + 18? -> o chain
            // needs its own shift: fold by adding (e has -18; odd scores
            // use o + (-18) explicitly here)
            uint32_t a0 = ex2h2(pkhf(e0, e1));
            uint32_t a1 = ex2h2(pkhf(e2, e3));
            uint32_t a2 = ex2h2(pkhf(o0 - 18.f, o1 - 18.f));
            uint32_t a3 = ex2h2(pkhf(o2 - 18.f, o3 - 18.f));
            MMA16816H(d[0], d[1], d[2], d[3], a0, a1, a2, a3, pb0, pb1);
        }
        __syncthreads();
    }

    // gather: t=0 lanes hold {A0,A1}; t=1 lanes hold {A2,l}; shuffle-combine
    {
        float az_r0 = __shfl_xor_sync(0xffffffffu, d[0], 1);  // from t^1
        float l_r0  = __shfl_xor_sync(0xffffffffu, d[1], 1);
        float az_r1 = __shfl_xor_sync(0xffffffffu, d[2], 1);
        float l_r1  = __shfl_xor_sync(0xffffffffu, d[3], 1);
        if (tq == 0) {
            size_t r = base + q0 + wid*16 + gq;
            g_part[(size_t)z*NROWS + r]     = make_float4(l_r0, d[0], d[1], az_r0);
            g_part[(size_t)z*NROWS + r + 8] = make_float4(l_r1, d[2], d[3], az_r1);
        }
    }
}

// ---------------------------------------------------------------------------
// Finalize: combine 2 split-K partials, normalize, add precomputed constant.
// ---------------------------------------------------------------------------
__global__ __launch_bounds__(256) void finalize_kernel(float* __restrict__ out) {
    const int tid = threadIdx.x;
    const float c0 = g_cst[0], c1 = g_cst[1], c2 = g_cst[2];
    size_t row = (size_t)blockIdx.x * 256 + tid;
    float4 p0 = g_part[row];
    float4 p1 = g_part[NROWS + row];
    float inv = 1.0f / (p0.x + p1.x);
    out[row*3 + 0] = fmaf(p0.y + p1.y, inv, c0);
    out[row*3 + 1] = fmaf(p0.z + p1.z, inv, c1);
    out[row*3 + 2] = fmaf(p0.w + p1.w, inv, c2);
}

extern "C" void kernel_launch(void* const* d_in, const int* in_sizes, int n_in,
                              void* d_out, int out_size) {
    const float* qin = (const float*)d_in[0];
    const float* kin = (const float*)d_in[1];
    const float* vin = (const float*)d_in[2];
    const float* Wq  = (const float*)d_in[3];
    const float* bq  = (const float*)d_in[4];
    const float* Wk  = (const float*)d_in[5];
    const float* bk  = (const float*)d_in[6];
    const float* Wv  = (const float*)d_in[7];
    const float* bv  = (const float*)d_in[8];
    const float* Wo  = (const float*)d_in[9];
    const float* bo  = (const float*)d_in[10];
    float* out = (float*)d_out;

    cudaFuncSetAttribute(flash11_kernel,
                         cudaFuncAttributeMaxDynamicSharedMemorySize, SMEM_BYTES);
    cudaFuncSetAttribute(proj6_kernel,
                         cudaFuncAttributeMaxDynamicSharedMemorySize, P6_SMEM);
    prep_kernel<<<1, 256>>>(Wq, Wk, Wv, Wo, bv, bo);
    proj6_kernel<<<dim3(NROWS/128, 3), 256, P6_SMEM>>>(qin, kin, vin, bq, bk);
    flash11_kernel<<<dim3(SS/128, BB, 2), 256, SMEM_BYTES>>>();
    finalize_kernel<<<NROWS/256, 256>>>(out);
}

// round 15
// speedup vs baseline: 1.1952x; 1.1226x over previous
#include <cuda_runtime.h>
#include <cuda_bf16.h>
#include <math.h>
#include <cstdint>

#define BB 32
#define SS 2048
#define FF 128
#define DK 32
#define NROWS (BB*SS)
#define SHIFT 4.0f     // softmax log2-domain shift (cancels in normalization)

// Packed projections, 64 bf16 per row (128B): [hi(32) | lo(32)]
// q pre-scaled by log2(e)/sqrt(32)  (scores in log2 domain -> ex2)
__device__ __nv_bfloat16 g_qp[NROWS*64];
__device__ __nv_bfloat16 g_kp[NROWS*64];
// PV B-operand, pre-packed fp16x2: per key-pair p, 8 cols g:
//   g<3: {lo=vw[2p][g], hi=vw[2p+1][g]}, g==3: {1,1}, g>3: 0
__device__ uint32_t g_vwp[(NROWS/2)*8];
__device__ float4 g_part[2*NROWS];         // split-K partials {l, A0, A1, A2}
// Pre-split W images (ldmatrix-ready): per phase 8704 bf16 = 4352 hi + 4352 lo,
// layout img[c*136 + f] (c = out col 0..31, f = 0..127, 8 pad per row)
__device__ __nv_bfloat16 g_wimg[2][8704];
__device__ float g_wveff[FF*3];            // Wv @ Wo_eff
__device__ float g_cst[3];                 // bo + bv . Wo_eff

static __device__ __forceinline__ uint32_t smem_u32(const void* p) {
    uint32_t a;
    asm("{ .reg .u64 t; cvta.to.shared.u64 t, %1; cvt.u32.u64 %0, t; }" : "=r"(a) : "l"(p));
    return a;
}
static __device__ __forceinline__ void cp16(uint32_t dst, const void* src) {
    asm volatile("cp.async.cg.shared.global [%0], [%1], 16;" :: "r"(dst), "l"(src) : "memory");
}
#define CP_COMMIT() asm volatile("cp.async.commit_group;" ::: "memory")
#define CP_WAIT(n)  asm volatile("cp.async.wait_group %0;" :: "n"(n) : "memory")

// pack {lo, hi} floats -> bf16x2
static __device__ __forceinline__ uint32_t pkbf(float lo, float hi) {
    uint32_t r;
    asm("cvt.rn.bf16x2.f32 %0, %1, %2;" : "=r"(r) : "f"(hi), "f"(lo));
    return r;
}
// pack {lo, hi} floats -> f16x2
static __device__ __forceinline__ uint32_t pkhf(float lo, float hi) {
    uint32_t r;
    asm("cvt.rn.f16x2.f32 %0, %1, %2;" : "=r"(r) : "f"(hi), "f"(lo));
    return r;
}
// packed fp16x2 exp2
static __device__ __forceinline__ uint32_t ex2h2(uint32_t x) {
    uint32_t y;
    asm("ex2.approx.f16x2 %0, %1;" : "=r"(y) : "r"(x));
    return y;
}
// split a float2 into bf16x2 hi + bf16x2 lo words
static __device__ __forceinline__ void split2(float2 x, uint32_t& h, uint32_t& l) {
    h = pkbf(x.x, x.y);
    float f0 = __uint_as_float(h << 16);
    float f1 = __uint_as_float(h & 0xFFFF0000u);
    l = pkbf(x.x - f0, x.y - f1);
}

#define LDSM_X4(r0,r1,r2,r3,addr) \
    asm volatile("ldmatrix.sync.aligned.m8n8.x4.shared.b16 {%0,%1,%2,%3}, [%4];" \
        : "=r"(r0), "=r"(r1), "=r"(r2), "=r"(r3) : "r"(addr))

#define MMA16816(c0,c1,c2,c3,a0,a1,a2,a3,b0,b1) \
    asm volatile("mma.sync.aligned.m16n8k16.row.col.f32.bf16.bf16.f32 " \
        "{%0,%1,%2,%3}, {%4,%5,%6,%7}, {%8,%9}, {%0,%1,%2,%3};" \
        : "+f"(c0), "+f"(c1), "+f"(c2), "+f"(c3) \
        : "r"(a0), "r"(a1), "r"(a2), "r"(a3), "r"(b0), "r"(b1))

#define MMA16816H(c0,c1,c2,c3,a0,a1,a2,a3,b0,b1) \
    asm volatile("mma.sync.aligned.m16n8k16.row.col.f32.f16.f16.f32 " \
        "{%0,%1,%2,%3}, {%4,%5,%6,%7}, {%8,%9}, {%0,%1,%2,%3};" \
        : "+f"(c0), "+f"(c1), "+f"(c2), "+f"(c3) \
        : "r"(a0), "r"(a1), "r"(a2), "r"(a3), "r"(b0), "r"(b1))

// ---------------------------------------------------------------------------
// Prep: grid 34. Blocks 0-31: one W-image column each (both phases).
// Block 32: Wv_eff. Block 33: output constant.
// ---------------------------------------------------------------------------
__global__ __launch_bounds__(256) void prep_kernel(
    const float* __restrict__ Wq, const float* __restrict__ Wk,
    const float* __restrict__ Wv, const float* __restrict__ Wo,
    const float* __restrict__ bv, const float* __restrict__ bo) {
    __shared__ float sWoE[DK*3];
    const int tid = threadIdx.x;
    const int b = blockIdx.x;
    if (b < 32) {
        int c = b;
        int ph = tid >> 7;         // 0 or 1
        int f  = tid & 127;
        const float* W = ph ? Wk : Wq;
        __nv_bfloat16* img = g_wimg[ph];
        float w = W[f*32 + c];
        __nv_bfloat16 h = __float2bfloat16(w);
        img[c*136 + f]        = h;
        img[4352 + c*136 + f] = __float2bfloat16(w - __bfloat162float(h));
    } else if (b == 32) {
        if (tid < 96) {
            int d = tid / 3, f = tid - d*3;
            float s = 0.f;
            #pragma unroll
            for (int h = 0; h < 16; ++h) s += Wo[(h*DK + d)*3 + f];
            sWoE[tid] = s;
        }
        __syncthreads();
        for (int i = tid; i < FF*3; i += 256) {
            int r = i / 3, f = i - r*3;
            float s = 0.f;
            #pragma unroll
            for (int d = 0; d < DK; ++d) s = fmaf(Wv[r*DK + d], sWoE[d*3 + f], s);
            g_wveff[i] = s;
        }
    } else {
        if (tid < 3) {
            float s = bo[tid];
            #pragma unroll
            for (int d = 0; d < DK; ++d) {
                float w = 0.f;
                #pragma unroll
                for (int h = 0; h < 16; ++h) w += Wo[(h*DK + d)*3 + tid];
                s = fmaf(bv[d], w, s);
            }
            g_cst[tid] = s;
        }
    }
}

// ---------------------------------------------------------------------------
// Projection: grid (512, 3), 256 threads, 128 rows/block.
// Q/K: A built in registers from global INSIDE the k-group loop (low reg
// pressure -> 4 blocks/SM); B from the pre-split W image. 3-term bf16 split.
// V: 4 threads/row + quad reduce, emits packed fp16 g_vwp fragments.
// ---------------------------------------------------------------------------
#define P6_SMEM 17536

__global__ __launch_bounds__(256, 4) void proj6_kernel(
    const float* __restrict__ qin, const float* __restrict__ kin, const float* __restrict__ vin,
    const float* __restrict__ bq, const float* __restrict__ bk) {
    extern __shared__ __align__(16) unsigned char dsm[];
    const int tid  = threadIdx.x;
    const int wid  = tid >> 5, lane = tid & 31;
    const int phase = blockIdx.y;
    const size_t row0 = (size_t)blockIdx.x * 128;
    const uint32_t sb = smem_u32(dsm);

    if (phase < 2) {
        const float* in = phase ? kin : qin;
        const float* bb = phase ? bk : bq;
        __nv_bfloat16* gout = phase ? g_kp : g_qp;
        const float qs = phase ? 1.0f
                               : 0.17677669529663687f * 1.4426950408889634f;

        // stage pre-split W image (17408 B)
        for (int i = tid; i < 1088; i += 256)
            cp16(sb + i*16, (const unsigned char*)g_wimg[phase] + i*16);
        CP_COMMIT();
        CP_WAIT(0);
        __syncthreads();

        const int gq = lane >> 2, tq = lane & 3;
        const int lr = lane & 7, sel = lane >> 3;
        const float* rp0 = in + (row0 + wid*16 + gq)*128;
        const float* rp1 = rp0 + 8*128;

        float acc[4][4];
        #pragma unroll
        for (int nt = 0; nt < 4; ++nt)
            #pragma unroll
            for (int i = 0; i < 4; ++i) acc[nt][i] = 0.f;

        #pragma unroll
        for (int g2 = 0; g2 < 4; ++g2) {
            uint32_t ah[2][4], al[2][4];
            #pragma unroll
            for (int gg = 0; gg < 2; ++gg) {
                int cb = (2*g2 + gg)*16 + tq*2;
                float2 x00 = *(const float2*)(rp0 + cb);
                float2 x10 = *(const float2*)(rp1 + cb);
                float2 x01 = *(const float2*)(rp0 + cb + 8);
                float2 x11 = *(const float2*)(rp1 + cb + 8);
                split2(x00, ah[gg][0], al[gg][0]);
                split2(x10, ah[gg][1], al[gg][1]);
                split2(x01, ah[gg][2], al[gg][2]);
                split2(x11, ah[gg][3], al[gg][3]);
            }
            #pragma unroll
            for (int nt = 0; nt < 4; ++nt) {
                uint32_t bwh = sb + (nt*8 + lr)*272 + sel*16 + g2*64;
                uint32_t bwl = bwh + 8704;
                uint32_t bh[4], bl[4];
                LDSM_X4(bh[0], bh[1], bh[2], bh[3], bwh);
                LDSM_X4(bl[0], bl[1], bl[2], bl[3], bwl);
                MMA16816(acc[nt][0],acc[nt][1],acc[nt][2],acc[nt][3],
                         ah[0][0],ah[0][1],ah[0][2],ah[0][3], bh[0],bh[1]); // xh.wh
                MMA16816(acc[nt][0],acc[nt][1],acc[nt][2],acc[nt][3],
                         ah[1][0],ah[1][1],ah[1][2],ah[1][3], bh[2],bh[3]);
                MMA16816(acc[nt][0],acc[nt][1],acc[nt][2],acc[nt][3],
                         ah[0][0],ah[0][1],ah[0][2],ah[0][3], bl[0],bl[1]); // xh.wl
                MMA16816(acc[nt][0],acc[nt][1],acc[nt][2],acc[nt][3],
                         ah[1][0],ah[1][1],ah[1][2],ah[1][3], bl[2],bl[3]);
                MMA16816(acc[nt][0],acc[nt][1],acc[nt][2],acc[nt][3],
                         al[0][0],al[0][1],al[0][2],al[0][3], bh[0],bh[1]); // xl.wh
                MMA16816(acc[nt][0],acc[nt][1],acc[nt][2],acc[nt][3],
                         al[1][0],al[1][1],al[1][2],al[1][3], bh[2],bh[3]);
            }
        }

        // epilogue: bias + scale, split hi/lo, packed u32 stores
        #pragma unroll
        for (int nt = 0; nt < 4; ++nt) {
            int colp = nt*8 + tq*2;
            float b0 = bb[colp], b1 = bb[colp+1];
            #pragma unroll
            for (int hf = 0; hf < 2; ++hf) {
                size_t rrow = row0 + wid*16 + gq + hf*8;
                float v0 = (acc[nt][hf*2+0] + b0) * qs;
                float v1 = (acc[nt][hf*2+1] + b1) * qs;
                uint32_t hp = pkbf(v0, v1);
                float h0 = __uint_as_float(hp << 16);
                float h1 = __uint_as_float(hp & 0xFFFF0000u);
                uint32_t lp = pkbf(v0 - h0, v1 - h1);
                *(uint32_t*)((unsigned char*)gout + rrow*128 + colp*2)      = hp;
                *(uint32_t*)((unsigned char*)gout + rrow*128 + 64 + colp*2) = lp;
            }
        }
    } else {
        // V: vw rows via 4 threads/row + quad reduce, then pack fp16 fragments
        float* sWv = (float*)dsm;                 // [384]
        float* sVS = (float*)(dsm + 1536);        // [128][4]
        for (int i = tid; i < 384; i += 256) sWv[i] = g_wveff[i];
        __syncthreads();
        #pragma unroll
        for (int it = 0; it < 2; ++it) {
            int r = it*64 + (tid >> 2);
            const float* rp = vin + (row0 + r)*128 + (tid & 3)*32;
            float a0 = 0.f, a1 = 0.f, a2 = 0.f;
            #pragma unroll
            for (int f4 = 0; f4 < 8; ++f4) {
                float4 x = ((const float4*)rp)[f4];
                int f = (tid & 3)*32 + f4*4;
                a0 = fmaf(x.x, sWv[(f+0)*3+0], a0); a1 = fmaf(x.x, sWv[(f+0)*3+1], a1); a2 = fmaf(x.x, sWv[(f+0)*3+2], a2);
                a0 = fmaf(x.y, sWv[(f+1)*3+0], a0); a1 = fmaf(x.y, sWv[(f+1)*3+1], a1); a2 = fmaf(x.y, sWv[(f+1)*3+2], a2);
                a0 = fmaf(x.z, sWv[(f+2)*3+0], a0); a1 = fmaf(x.z, sWv[(f+2)*3+1], a1); a2 = fmaf(x.z, sWv[(f+2)*3+2], a2);
                a0 = fmaf(x.w, sWv[(f+3)*3+0], a0); a1 = fmaf(x.w, sWv[(f+3)*3+1], a1); a2 = fmaf(x.w, sWv[(f+3)*3+2], a2);
            }
            a0 += __shfl_xor_sync(0xffffffffu, a0, 1); a0 += __shfl_xor_sync(0xffffffffu, a0, 2);
            a1 += __shfl_xor_sync(0xffffffffu, a1, 1); a1 += __shfl_xor_sync(0xffffffffu, a1, 2);
            a2 += __shfl_xor_sync(0xffffffffu, a2, 1); a2 += __shfl_xor_sync(0xffffffffu, a2, 2);
            if ((tid & 3) == 0) {
                sVS[r*4 + 0] = a0; sVS[r*4 + 1] = a1; sVS[r*4 + 2] = a2;
            }
        }
        __syncthreads();
        for (int i = tid; i < 512; i += 256) {
            int p = i >> 3, g = i & 7;
            uint32_t w;
            if (g < 3)       w = pkhf(sVS[(2*p)*4 + g], sVS[(2*p+1)*4 + g]);
            else if (g == 3) w = 0x3C003C00u;       // {1.0h, 1.0h}
            else             w = 0u;
            g_vwp[(row0 >> 1)*8 + i] = w;
        }
    }
}

// ---------------------------------------------------------------------------
// Flash kernel: 256 threads (8 warps x 16 q-rows), q-tile 128, split-K 2-way.
// Q staged in ring buffer 1, K0 prefetched concurrently into buffer 0.
// QK^T bf16-split HMMA; softmax via packed ex2.f16x2 (scores shifted by
// -SHIFT, cancels in normalization); PV via fp16 HMMA with packed vwp.
// ---------------------------------------------------------------------------
#define RSTRK 144
#define KTILEB (128*RSTRK)                 // 18432
#define RINGSTRIDE (KTILEB + 2048)         // 20480 (K tile + vwp)
#define SMEM_BYTES (2*RINGSTRIDE)          // 40960

__global__ __launch_bounds__(256, 4)
void flash12_kernel(void) {
    extern __shared__ __align__(16) unsigned char smem[];
    const int tid  = threadIdx.x;
    const int wid  = tid >> 5, lane = tid & 31;
    const size_t base = (size_t)blockIdx.y * SS;
    const int q0 = blockIdx.x * 128;
    const int z  = blockIdx.z;
    const uint32_t sbase = smem_u32(smem);

    // stage Q tile (16 KB) in ring buffer 1
    #pragma unroll
    for (int k = 0; k < 4; ++k) {
        int i = tid + k*256;
        cp16(sbase + RINGSTRIDE + i*16,
             (const unsigned char*)g_qp + (base + q0)*128 + i*16);
    }
    CP_COMMIT();
    // concurrently prefetch K tile 0 + vwp into ring buffer 0
    {
        const size_t kb = base + (size_t)z * 1024;
        #pragma unroll
        for (int k = 0; k < 4; ++k) {
            int i = tid + k*256;
            int rr = i >> 3, sg = i & 7;
            cp16(sbase + rr*RSTRK + sg*16,
                 (const unsigned char*)g_kp + (kb + rr)*128 + sg*16);
        }
        if (tid < 128)
            cp16(sbase + KTILEB + tid*16, g_vwp + (kb >> 1)*8 + tid*4);
    }
    CP_COMMIT();
    CP_WAIT(1);   // Q ready (K0 may still be in flight)
    __syncthreads();

    const int lr  = lane & 7;
    const int sel = lane >> 3;

    // A fragments (loop-invariant): qh steps {0,1}, ql steps {0,1}
    uint32_t aF[4][4];
    {
        int arow = wid*16 + lr + (sel & 1)*8;
        uint32_t abase = sbase + RINGSTRIDE + arow*128 + (sel >> 1)*16;
        #pragma unroll
        for (int g = 0; g < 4; ++g)
            LDSM_X4(aF[g][0], aF[g][1], aF[g][2], aF[g][3], abase + g*32);
    }
    __syncthreads();   // all warps done reading Q region (buffer 1)

    // PV accumulators: cols 2t,2t+1 (t=lane&3): t=0 -> {A0,A1}, t=1 -> {A2,l}
    float d[4] = {0.f, 0.f, 0.f, 0.f};
    const int tq = lane & 3, gq = lane >> 2;

    #pragma unroll 1
    for (int ti = 0; ti < 8; ++ti) {
        if (ti < 7) {
            const size_t kb = base + (size_t)z*1024 + (size_t)(ti+1)*128;
            uint32_t db = sbase + ((ti+1) & 1)*RINGSTRIDE;
            #pragma unroll
            for (int k = 0; k < 4; ++k) {
                int i = tid + k*256;
                int rr = i >> 3, sg = i & 7;
                cp16(db + rr*RSTRK + sg*16,
                     (const unsigned char*)g_kp + (kb + rr)*128 + sg*16);
            }
            if (tid < 128)
                cp16(db + KTILEB + tid*16, g_vwp + (kb >> 1)*8 + tid*4);
            CP_COMMIT();
            CP_WAIT(1);
        } else {
            CP_WAIT(0);
        }
        __syncthreads();

        const uint32_t sk  = sbase + (ti & 1)*RINGSTRIDE;
        const uint32_t svw = sk + KTILEB;

        #pragma unroll 2
        for (int jp = 0; jp < 8; ++jp) {
            uint32_t be[8], bo_[8];
            {
                uint32_t bb = sk + ((2*jp)*8 + lr)*RSTRK + sel*16;
                LDSM_X4(be[0], be[1], be[2], be[3], bb);
                LDSM_X4(be[4], be[5], be[6], be[7], bb + 64);
                uint32_t bb2 = sk + ((2*jp+1)*8 + lr)*RSTRK + sel*16;
                LDSM_X4(bo_[0], bo_[1], bo_[2], bo_[3], bb2);
                LDSM_X4(bo_[4], bo_[5], bo_[6], bo_[7], bb2 + 64);
            }
            uint32_t pb0, pb1;
            asm volatile("ld.shared.b32 %0, [%1];" : "=r"(pb0)
                         : "r"(svw + ((jp*8 + tq)*8 + gq)*4));
            asm volatile("ld.shared.b32 %0, [%1];" : "=r"(pb1)
                         : "r"(svw + ((jp*8 + 4 + tq)*8 + gq)*4));

            // e-chain pre-shifted by -SHIFT (softmax shift-invariant; keeps
            // exp2 results in fp16 normal range: typical p ~ 2^-4)
            float e0=-SHIFT,e1=-SHIFT,e2=-SHIFT,e3=-SHIFT;  // j even scores
            float o0=0.f,o1=0.f,o2=0.f,o3=0.f;              // j odd part
            MMA16816(e0,e1,e2,e3, aF[0][0],aF[0][1],aF[0][2],aF[0][3], be[0],be[1]);
            MMA16816(o0,o1,o2,o3, aF[0][0],aF[0][1],aF[0][2],aF[0][3], bo_[0],bo_[1]);
            MMA16816(e0,e1,e2,e3, aF[1][0],aF[1][1],aF[1][2],aF[1][3], be[2],be[3]);
            MMA16816(o0,o1,o2,o3, aF[1][0],aF[1][1],aF[1][2],aF[1][3], bo_[2],bo_[3]);
            MMA16816(e0,e1,e2,e3, aF[0][0],aF[0][1],aF[0][2],aF[0][3], be[4],be[5]);
            MMA16816(o0,o1,o2,o3, aF[0][0],aF[0][1],aF[0][2],aF[0][3], bo_[4],bo_[5]);
            MMA16816(e0,e1,e2,e3, aF[1][0],aF[1][1],aF[1][2],aF[1][3], be[6],be[7]);
            MMA16816(o0,o1,o2,o3, aF[1][0],aF[1][1],aF[1][2],aF[1][3], bo_[6],bo_[7]);
            MMA16816(e0,e1,e2,e3, aF[2][0],aF[2][1],aF[2][2],aF[2][3], be[0],be[1]);
            MMA16816(o0,o1,o2,o3, aF[2][0],aF[2][1],aF[2][2],aF[2][3], bo_[0],bo_[1]);
            MMA16816(e0,e1,e2,e3, aF[3][0],aF[3][1],aF[3][2],aF[3][3], be[2],be[3]);
            MMA16816(o0,o1,o2,o3, aF[3][0],aF[3][1],aF[3][2],aF[3][3], bo_[2],bo_[3]);

            uint32_t a0 = ex2h2(pkhf(e0, e1));
            uint32_t a1 = ex2h2(pkhf(e2, e3));
            uint32_t a2 = ex2h2(pkhf(o0 - SHIFT, o1 - SHIFT));
            uint32_t a3 = ex2h2(pkhf(o2 - SHIFT, o3 - SHIFT));
            MMA16816H(d[0], d[1], d[2], d[3], a0, a1, a2, a3, pb0, pb1);
        }
        __syncthreads();
    }

    // gather: t=0 lanes hold {A0,A1}; t=1 lanes hold {A2,l}; shuffle-combine
    {
        float az_r0 = __shfl_xor_sync(0xffffffffu, d[0], 1);  // from t^1
        float l_r0  = __shfl_xor_sync(0xffffffffu, d[1], 1);
        float az_r1 = __shfl_xor_sync(0xffffffffu, d[2], 1);
        float l_r1  = __shfl_xor_sync(0xffffffffu, d[3], 1);
        if (tq == 0) {
            size_t r = base + q0 + wid*16 + gq;
            g_part[(size_t)z*NROWS + r]     = make_float4(l_r0, d[0], d[1], az_r0);
            g_part[(size_t)z*NROWS + r + 8] = make_float4(l_r1, d[2], d[3], az_r1);
        }
    }
}

// ---------------------------------------------------------------------------
// Finalize: combine 2 split-K partials, normalize, add precomputed constant.
// ---------------------------------------------------------------------------
__global__ __launch_bounds__(256) void finalize_kernel(float* __restrict__ out) {
    const int tid = threadIdx.x;
    const float c0 = g_cst[0], c1 = g_cst[1], c2 = g_cst[2];
    size_t row = (size_t)blockIdx.x * 256 + tid;
    float4 p0 = g_part[row];
    float4 p1 = g_part[NROWS + row];
    float inv = 1.0f / (p0.x + p1.x);
    out[row*3 + 0] = fmaf(p0.y + p1.y, inv, c0);
    out[row*3 + 1] = fmaf(p0.z + p1.z, inv, c1);
    out[row*3 + 2] = fmaf(p0.w + p1.w, inv, c2);
}

extern "C" void kernel_launch(void* const* d_in, const int* in_sizes, int n_in,
                              void* d_out, int out_size) {
    const float* qin = (const float*)d_in[0];
    const float* kin = (const float*)d_in[1];
    const float* vin = (const float*)d_in[2];
    const float* Wq  = (const float*)d_in[3];
    const float* bq  = (const float*)d_in[4];
    const float* Wk  = (const float*)d_in[5];
    const float* bk  = (const float*)d_in[6];
    const float* Wv  = (const float*)d_in[7];
    const float* bv  = (const float*)d_in[8];
    const float* Wo  = (const float*)d_in[9];
    const float* bo  = (const float*)d_in[10];
    float* out = (float*)d_out;

    cudaFuncSetAttribute(flash12_kernel,
                         cudaFuncAttributeMaxDynamicSharedMemorySize, SMEM_BYTES);
    cudaFuncSetAttribute(proj6_kernel,
                         cudaFuncAttributeMaxDynamicSharedMemorySize, P6_SMEM);
    prep_kernel<<<34, 256>>>(Wq, Wk, Wv, Wo, bv, bo);
    proj6_kernel<<<dim3(NROWS/128, 3), 256, P6_SMEM>>>(qin, kin, vin, bq, bk);
    flash12_kernel<<<dim3(SS/128, BB, 2), 256, SMEM_BYTES>>>();
    finalize_kernel<<<NROWS/256, 256>>>(out);
}

// round 16
// speedup vs baseline: 1.1991x; 1.0033x over previous
#include <cuda_runtime.h>
#include <cuda_bf16.h>
#include <math.h>
#include <cstdint>

#define BB 32
#define SS 2048
#define FF 128
#define DK 32
#define NROWS (BB*SS)
#define SHIFT 4.0f     // softmax log2-domain shift (cancels in normalization)

// Packed projections, 64 bf16 per row (128B): [hi(32) | lo(32)]
// q pre-scaled by log2(e)/sqrt(32)  (scores in log2 domain -> ex2)
__device__ __nv_bfloat16 g_qp[NROWS*64];
__device__ __nv_bfloat16 g_kp[NROWS*64];
// PV B-operand, pre-packed fp16x2: per key-pair p, 8 cols g:
//   g<3: {lo=vw[2p][g], hi=vw[2p+1][g]}, g==3: {1,1}, g>3: 0
__device__ uint32_t g_vwp[(NROWS/2)*8];
__device__ float4 g_part[2*NROWS];         // split-K partials {l, A0, A1, A2}
// Pre-split W images (ldmatrix-ready): per phase 8704 bf16 = 4352 hi + 4352 lo,
// layout img[c*136 + f] (c = out col 0..31, f = 0..127, 8 pad per row)
__device__ __nv_bfloat16 g_wimg[2][8704];
__device__ float g_wveff[FF*3];            // Wv @ Wo_eff
__device__ float g_cst[3];                 // bo + bv . Wo_eff

static __device__ __forceinline__ uint32_t smem_u32(const void* p) {
    uint32_t a;
    asm("{ .reg .u64 t; cvta.to.shared.u64 t, %1; cvt.u32.u64 %0, t; }" : "=r"(a) : "l"(p));
    return a;
}
static __device__ __forceinline__ void cp16(uint32_t dst, const void* src) {
    asm volatile("cp.async.cg.shared.global [%0], [%1], 16;" :: "r"(dst), "l"(src) : "memory");
}
#define CP_COMMIT() asm volatile("cp.async.commit_group;" ::: "memory")
#define CP_WAIT(n)  asm volatile("cp.async.wait_group %0;" :: "n"(n) : "memory")

// pack {lo, hi} floats -> bf16x2
static __device__ __forceinline__ uint32_t pkbf(float lo, float hi) {
    uint32_t r;
    asm("cvt.rn.bf16x2.f32 %0, %1, %2;" : "=r"(r) : "f"(hi), "f"(lo));
    return r;
}
// pack {lo, hi} floats -> f16x2
static __device__ __forceinline__ uint32_t pkhf(float lo, float hi) {
    uint32_t r;
    asm("cvt.rn.f16x2.f32 %0, %1, %2;" : "=r"(r) : "f"(hi), "f"(lo));
    return r;
}
// packed fp16x2 exp2
static __device__ __forceinline__ uint32_t ex2h2(uint32_t x) {
    uint32_t y;
    asm("ex2.approx.f16x2 %0, %1;" : "=r"(y) : "r"(x));
    return y;
}
// split a float2 into bf16x2 hi + bf16x2 lo words
static __device__ __forceinline__ void split2(float2 x, uint32_t& h, uint32_t& l) {
    h = pkbf(x.x, x.y);
    float f0 = __uint_as_float(h << 16);
    float f1 = __uint_as_float(h & 0xFFFF0000u);
    l = pkbf(x.x - f0, x.y - f1);
}

#define LDSM_X4(r0,r1,r2,r3,addr) \
    asm volatile("ldmatrix.sync.aligned.m8n8.x4.shared.b16 {%0,%1,%2,%3}, [%4];" \
        : "=r"(r0), "=r"(r1), "=r"(r2), "=r"(r3) : "r"(addr))

#define MMA16816(c0,c1,c2,c3,a0,a1,a2,a3,b0,b1) \
    asm volatile("mma.sync.aligned.m16n8k16.row.col.f32.bf16.bf16.f32 " \
        "{%0,%1,%2,%3}, {%4,%5,%6,%7}, {%8,%9}, {%0,%1,%2,%3};" \
        : "+f"(c0), "+f"(c1), "+f"(c2), "+f"(c3) \
        : "r"(a0), "r"(a1), "r"(a2), "r"(a3), "r"(b0), "r"(b1))

#define MMA16816H(c0,c1,c2,c3,a0,a1,a2,a3,b0,b1) \
    asm volatile("mma.sync.aligned.m16n8k16.row.col.f32.f16.f16.f32 " \
        "{%0,%1,%2,%3}, {%4,%5,%6,%7}, {%8,%9}, {%0,%1,%2,%3};" \
        : "+f"(c0), "+f"(c1), "+f"(c2), "+f"(c3) \
        : "r"(a0), "r"(a1), "r"(a2), "r"(a3), "r"(b0), "r"(b1))

// ---------------------------------------------------------------------------
// Prep: grid 34. Blocks 0-31: one W-image column each (both phases).
// Block 32: Wv_eff. Block 33: output constant.
// ---------------------------------------------------------------------------
__global__ __launch_bounds__(256) void prep_kernel(
    const float* __restrict__ Wq, const float* __restrict__ Wk,
    const float* __restrict__ Wv, const float* __restrict__ Wo,
    const float* __restrict__ bv, const float* __restrict__ bo) {
    __shared__ float sWoE[DK*3];
    const int tid = threadIdx.x;
    const int b = blockIdx.x;
    if (b < 32) {
        int c = b;
        int ph = tid >> 7;         // 0 or 1
        int f  = tid & 127;
        const float* W = ph ? Wk : Wq;
        __nv_bfloat16* img = g_wimg[ph];
        float w = W[f*32 + c];
        __nv_bfloat16 h = __float2bfloat16(w);
        img[c*136 + f]        = h;
        img[4352 + c*136 + f] = __float2bfloat16(w - __bfloat162float(h));
    } else if (b == 32) {
        if (tid < 96) {
            int d = tid / 3, f = tid - d*3;
            float s = 0.f;
            #pragma unroll
            for (int h = 0; h < 16; ++h) s += Wo[(h*DK + d)*3 + f];
            sWoE[tid] = s;
        }
        __syncthreads();
        for (int i = tid; i < FF*3; i += 256) {
            int r = i / 3, f = i - r*3;
            float s = 0.f;
            #pragma unroll
            for (int d = 0; d < DK; ++d) s = fmaf(Wv[r*DK + d], sWoE[d*3 + f], s);
            g_wveff[i] = s;
        }
    } else {
        if (tid < 3) {
            float s = bo[tid];
            #pragma unroll
            for (int d = 0; d < DK; ++d) {
                float w = 0.f;
                #pragma unroll
                for (int h = 0; h < 16; ++h) w += Wo[(h*DK + d)*3 + tid];
                s = fmaf(bv[d], w, s);
            }
            g_cst[tid] = s;
        }
    }
}

// ---------------------------------------------------------------------------
// Projection (merged): grid 512, 256 threads, 128 rows/block, ALL phases
// (Q, K, V) in one block -> single wave (512 < 592 resident), W staged once.
// ---------------------------------------------------------------------------
#define P7_WQ 0
#define P7_WK 17408
#define P7_WV 34816                     // Wv_eff: 384 floats
#define P7_VS 36352                     // vw staging: 128*4 floats
#define P7_SMEM 38400

__global__ __launch_bounds__(256, 4) void proj7_kernel(
    const float* __restrict__ qin, const float* __restrict__ kin, const float* __restrict__ vin,
    const float* __restrict__ bq, const float* __restrict__ bk) {
    extern __shared__ __align__(16) unsigned char dsm[];
    const int tid  = threadIdx.x;
    const int wid  = tid >> 5, lane = tid & 31;
    const size_t row0 = (size_t)blockIdx.x * 128;
    const uint32_t sb = smem_u32(dsm);

    // stage both W images (34816 B) + Wv_eff (1536 B)
    for (int i = tid; i < 2176; i += 256)
        cp16(sb + i*16, (const unsigned char*)g_wimg[0] + i*16);
    for (int i = tid; i < 96; i += 256)
        cp16(sb + P7_WV + i*16, (const unsigned char*)g_wveff + i*16);
    CP_COMMIT();
    CP_WAIT(0);
    __syncthreads();

    const int gq = lane >> 2, tq = lane & 3;
    const int lr = lane & 7, sel = lane >> 3;

    // ---------------- Q and K phases ----------------
    #pragma unroll 1
    for (int phase = 0; phase < 2; ++phase) {
        const float* in = phase ? kin : qin;
        const float* bb = phase ? bk : bq;
        __nv_bfloat16* gout = phase ? g_kp : g_qp;
        const float qs = phase ? 1.0f
                               : 0.17677669529663687f * 1.4426950408889634f;
        const uint32_t wbase = sb + phase*17408;

        const float* rp0 = in + (row0 + wid*16 + gq)*128;
        const float* rp1 = rp0 + 8*128;

        float acc[4][4];
        #pragma unroll
        for (int nt = 0; nt < 4; ++nt)
            #pragma unroll
            for (int i = 0; i < 4; ++i) acc[nt][i] = 0.f;

        #pragma unroll
        for (int g2 = 0; g2 < 4; ++g2) {
            uint32_t ah[2][4], al[2][4];
            #pragma unroll
            for (int gg = 0; gg < 2; ++gg) {
                int cb = (2*g2 + gg)*16 + tq*2;
                float2 x00 = *(const float2*)(rp0 + cb);
                float2 x10 = *(const float2*)(rp1 + cb);
                float2 x01 = *(const float2*)(rp0 + cb + 8);
                float2 x11 = *(const float2*)(rp1 + cb + 8);
                split2(x00, ah[gg][0], al[gg][0]);
                split2(x10, ah[gg][1], al[gg][1]);
                split2(x01, ah[gg][2], al[gg][2]);
                split2(x11, ah[gg][3], al[gg][3]);
            }
            #pragma unroll
            for (int nt = 0; nt < 4; ++nt) {
                uint32_t bwh = wbase + (nt*8 + lr)*272 + sel*16 + g2*64;
                uint32_t bwl = bwh + 8704;
                uint32_t bh[4], bl[4];
                LDSM_X4(bh[0], bh[1], bh[2], bh[3], bwh);
                LDSM_X4(bl[0], bl[1], bl[2], bl[3], bwl);
                MMA16816(acc[nt][0],acc[nt][1],acc[nt][2],acc[nt][3],
                         ah[0][0],ah[0][1],ah[0][2],ah[0][3], bh[0],bh[1]); // xh.wh
                MMA16816(acc[nt][0],acc[nt][1],acc[nt][2],acc[nt][3],
                         ah[1][0],ah[1][1],ah[1][2],ah[1][3], bh[2],bh[3]);
                MMA16816(acc[nt][0],acc[nt][1],acc[nt][2],acc[nt][3],
                         ah[0][0],ah[0][1],ah[0][2],ah[0][3], bl[0],bl[1]); // xh.wl
                MMA16816(acc[nt][0],acc[nt][1],acc[nt][2],acc[nt][3],
                         ah[1][0],ah[1][1],ah[1][2],ah[1][3], bl[2],bl[3]);
                MMA16816(acc[nt][0],acc[nt][1],acc[nt][2],acc[nt][3],
                         al[0][0],al[0][1],al[0][2],al[0][3], bh[0],bh[1]); // xl.wh
                MMA16816(acc[nt][0],acc[nt][1],acc[nt][2],acc[nt][3],
                         al[1][0],al[1][1],al[1][2],al[1][3], bh[2],bh[3]);
            }
        }

        // epilogue: bias + scale, split hi/lo, packed u32 stores
        #pragma unroll
        for (int nt = 0; nt < 4; ++nt) {
            int colp = nt*8 + tq*2;
            float b0 = bb[colp], b1 = bb[colp+1];
            #pragma unroll
            for (int hf = 0; hf < 2; ++hf) {
                size_t rrow = row0 + wid*16 + gq + hf*8;
                float v0 = (acc[nt][hf*2+0] + b0) * qs;
                float v1 = (acc[nt][hf*2+1] + b1) * qs;
                uint32_t hp = pkbf(v0, v1);
                float h0 = __uint_as_float(hp << 16);
                float h1 = __uint_as_float(hp & 0xFFFF0000u);
                uint32_t lp = pkbf(v0 - h0, v1 - h1);
                *(uint32_t*)((unsigned char*)gout + rrow*128 + colp*2)      = hp;
                *(uint32_t*)((unsigned char*)gout + rrow*128 + 64 + colp*2) = lp;
            }
        }
    }

    // ---------------- V phase ----------------
    {
        float* sWv = (float*)(dsm + P7_WV);
        float* sVS = (float*)(dsm + P7_VS);
        #pragma unroll
        for (int it = 0; it < 2; ++it) {
            int r = it*64 + (tid >> 2);
            const float* rp = vin + (row0 + r)*128 + (tid & 3)*32;
            float a0 = 0.f, a1 = 0.f, a2 = 0.f;
            #pragma unroll
            for (int f4 = 0; f4 < 8; ++f4) {
                float4 x = ((const float4*)rp)[f4];
                int f = (tid & 3)*32 + f4*4;
                a0 = fmaf(x.x, sWv[(f+0)*3+0], a0); a1 = fmaf(x.x, sWv[(f+0)*3+1], a1); a2 = fmaf(x.x, sWv[(f+0)*3+2], a2);
                a0 = fmaf(x.y, sWv[(f+1)*3+0], a0); a1 = fmaf(x.y, sWv[(f+1)*3+1], a1); a2 = fmaf(x.y, sWv[(f+1)*3+2], a2);
                a0 = fmaf(x.z, sWv[(f+2)*3+0], a0); a1 = fmaf(x.z, sWv[(f+2)*3+1], a1); a2 = fmaf(x.z, sWv[(f+2)*3+2], a2);
                a0 = fmaf(x.w, sWv[(f+3)*3+0], a0); a1 = fmaf(x.w, sWv[(f+3)*3+1], a1); a2 = fmaf(x.w, sWv[(f+3)*3+2], a2);
            }
            a0 += __shfl_xor_sync(0xffffffffu, a0, 1); a0 += __shfl_xor_sync(0xffffffffu, a0, 2);
            a1 += __shfl_xor_sync(0xffffffffu, a1, 1); a1 += __shfl_xor_sync(0xffffffffu, a1, 2);
            a2 += __shfl_xor_sync(0xffffffffu, a2, 1); a2 += __shfl_xor_sync(0xffffffffu, a2, 2);
            if ((tid & 3) == 0) {
                sVS[r*4 + 0] = a0; sVS[r*4 + 1] = a1; sVS[r*4 + 2] = a2;
            }
        }
        __syncthreads();
        for (int i = tid; i < 512; i += 256) {
            int p = i >> 3, g = i & 7;
            uint32_t w;
            if (g < 3)       w = pkhf(sVS[(2*p)*4 + g], sVS[(2*p+1)*4 + g]);
            else if (g == 3) w = 0x3C003C00u;       // {1.0h, 1.0h}
            else             w = 0u;
            g_vwp[(row0 >> 1)*8 + i] = w;
        }
    }
}

// ---------------------------------------------------------------------------
// Flash kernel: 256 threads (8 warps x 16 q-rows), q-tile 128, split-K 2-way.
// Q staged in ring buffer 1, K0 prefetched concurrently into buffer 0.
// QK^T bf16-split HMMA; softmax via packed ex2.f16x2 (scores shifted by
// -SHIFT, cancels in normalization); PV via fp16 HMMA with packed vwp.
// ---------------------------------------------------------------------------
#define RSTRK 144
#define KTILEB (128*RSTRK)                 // 18432
#define RINGSTRIDE (KTILEB + 2048)         // 20480 (K tile + vwp)
#define SMEM_BYTES (2*RINGSTRIDE)          // 40960

__global__ __launch_bounds__(256, 4)
void flash12_kernel(void) {
    extern __shared__ __align__(16) unsigned char smem[];
    const int tid  = threadIdx.x;
    const int wid  = tid >> 5, lane = tid & 31;
    const size_t base = (size_t)blockIdx.y * SS;
    const int q0 = blockIdx.x * 128;
    const int z  = blockIdx.z;
    const uint32_t sbase = smem_u32(smem);

    // stage Q tile (16 KB) in ring buffer 1
    #pragma unroll
    for (int k = 0; k < 4; ++k) {
        int i = tid + k*256;
        cp16(sbase + RINGSTRIDE + i*16,
             (const unsigned char*)g_qp + (base + q0)*128 + i*16);
    }
    CP_COMMIT();
    // concurrently prefetch K tile 0 + vwp into ring buffer 0
    {
        const size_t kb = base + (size_t)z * 1024;
        #pragma unroll
        for (int k = 0; k < 4; ++k) {
            int i = tid + k*256;
            int rr = i >> 3, sg = i & 7;
            cp16(sbase + rr*RSTRK + sg*16,
                 (const unsigned char*)g_kp + (kb + rr)*128 + sg*16);
        }
        if (tid < 128)
            cp16(sbase + KTILEB + tid*16, g_vwp + (kb >> 1)*8 + tid*4);
    }
    CP_COMMIT();
    CP_WAIT(1);   // Q ready (K0 may still be in flight)
    __syncthreads();

    const int lr  = lane & 7;
    const int sel = lane >> 3;

    // A fragments (loop-invariant): qh steps {0,1}, ql steps {0,1}
    uint32_t aF[4][4];
    {
        int arow = wid*16 + lr + (sel & 1)*8;
        uint32_t abase = sbase + RINGSTRIDE + arow*128 + (sel >> 1)*16;
        #pragma unroll
        for (int g = 0; g < 4; ++g)
            LDSM_X4(aF[g][0], aF[g][1], aF[g][2], aF[g][3], abase + g*32);
    }
    __syncthreads();   // all warps done reading Q region (buffer 1)

    // PV accumulators: cols 2t,2t+1 (t=lane&3): t=0 -> {A0,A1}, t=1 -> {A2,l}
    float d[4] = {0.f, 0.f, 0.f, 0.f};
    const int tq = lane & 3, gq = lane >> 2;

    #pragma unroll 1
    for (int ti = 0; ti < 8; ++ti) {
        if (ti < 7) {
            const size_t kb = base + (size_t)z*1024 + (size_t)(ti+1)*128;
            uint32_t db = sbase + ((ti+1) & 1)*RINGSTRIDE;
            #pragma unroll
            for (int k = 0; k < 4; ++k) {
                int i = tid + k*256;
                int rr = i >> 3, sg = i & 7;
                cp16(db + rr*RSTRK + sg*16,
                     (const unsigned char*)g_kp + (kb + rr)*128 + sg*16);
            }
            if (tid < 128)
                cp16(db + KTILEB + tid*16, g_vwp + (kb >> 1)*8 + tid*4);
            CP_COMMIT();
            CP_WAIT(1);
        } else {
            CP_WAIT(0);
        }
        __syncthreads();

        const uint32_t sk  = sbase + (ti & 1)*RINGSTRIDE;
        const uint32_t svw = sk + KTILEB;

        #pragma unroll 2
        for (int jp = 0; jp < 8; ++jp) {
            uint32_t be[8], bo_[8];
            {
                uint32_t bb = sk + ((2*jp)*8 + lr)*RSTRK + sel*16;
                LDSM_X4(be[0], be[1], be[2], be[3], bb);
                LDSM_X4(be[4], be[5], be[6], be[7], bb + 64);
                uint32_t bb2 = sk + ((2*jp+1)*8 + lr)*RSTRK + sel*16;
                LDSM_X4(bo_[0], bo_[1], bo_[2], bo_[3], bb2);
                LDSM_X4(bo_[4], bo_[5], bo_[6], bo_[7], bb2 + 64);
            }
            uint32_t pb0, pb1;
            asm volatile("ld.shared.b32 %0, [%1];" : "=r"(pb0)
                         : "r"(svw + ((jp*8 + tq)*8 + gq)*4));
            asm volatile("ld.shared.b32 %0, [%1];" : "=r"(pb1)
                         : "r"(svw + ((jp*8 + 4 + tq)*8 + gq)*4));

            // e-chain pre-shifted by -SHIFT (softmax shift-invariant; keeps
            // exp2 results in fp16 normal range: typical p ~ 2^-4)
            float e0=-SHIFT,e1=-SHIFT,e2=-SHIFT,e3=-SHIFT;  // j even scores
            float o0=0.f,o1=0.f,o2=0.f,o3=0.f;              // j odd part
            MMA16816(e0,e1,e2,e3, aF[0][0],aF[0][1],aF[0][2],aF[0][3], be[0],be[1]);
            MMA16816(o0,o1,o2,o3, aF[0][0],aF[0][1],aF[0][2],aF[0][3], bo_[0],bo_[1]);
            MMA16816(e0,e1,e2,e3, aF[1][0],aF[1][1],aF[1][2],aF[1][3], be[2],be[3]);
            MMA16816(o0,o1,o2,o3, aF[1][0],aF[1][1],aF[1][2],aF[1][3], bo_[2],bo_[3]);
            MMA16816(e0,e1,e2,e3, aF[0][0],aF[0][1],aF[0][2],aF[0][3], be[4],be[5]);
            MMA16816(o0,o1,o2,o3, aF[0][0],aF[0][1],aF[0][2],aF[0][3], bo_[4],bo_[5]);
            MMA16816(e0,e1,e2,e3, aF[1][0],aF[1][1],aF[1][2],aF[1][3], be[6],be[7]);
            MMA16816(o0,o1,o2,o3, aF[1][0],aF[1][1],aF[1][2],aF[1][3], bo_[6],bo_[7]);
            MMA16816(e0,e1,e2,e3, aF[2][0],aF[2][1],aF[2][2],aF[2][3], be[0],be[1]);
            MMA16816(o0,o1,o2,o3, aF[2][0],aF[2][1],aF[2][2],aF[2][3], bo_[0],bo_[1]);
            MMA16816(e0,e1,e2,e3, aF[3][0],aF[3][1],aF[3][2],aF[3][3], be[2],be[3]);
            MMA16816(o0,o1,o2,o3, aF[3][0],aF[3][1],aF[3][2],aF[3][3], bo_[2],bo_[3]);

            uint32_t a0 = ex2h2(pkhf(e0, e1));
            uint32_t a1 = ex2h2(pkhf(e2, e3));
            uint32_t a2 = ex2h2(pkhf(o0 - SHIFT, o1 - SHIFT));
            uint32_t a3 = ex2h2(pkhf(o2 - SHIFT, o3 - SHIFT));
            MMA16816H(d[0], d[1], d[2], d[3], a0, a1, a2, a3, pb0, pb1);
        }
        __syncthreads();
    }

    // gather: t=0 lanes hold {A0,A1}; t=1 lanes hold {A2,l}; shuffle-combine
    {
        float az_r0 = __shfl_xor_sync(0xffffffffu, d[0], 1);  // from t^1
        float l_r0  = __shfl_xor_sync(0xffffffffu, d[1], 1);
        float az_r1 = __shfl_xor_sync(0xffffffffu, d[2], 1);
        float l_r1  = __shfl_xor_sync(0xffffffffu, d[3], 1);
        if (tq == 0) {
            size_t r = base + q0 + wid*16 + gq;
            g_part[(size_t)z*NROWS + r]     = make_float4(l_r0, d[0], d[1], az_r0);
            g_part[(size_t)z*NROWS + r + 8] = make_float4(l_r1, d[2], d[3], az_r1);
        }
    }
}

// ---------------------------------------------------------------------------
// Finalize: combine 2 split-K partials, normalize, add precomputed constant.
// ---------------------------------------------------------------------------
__global__ __launch_bounds__(256) void finalize_kernel(float* __restrict__ out) {
    const int tid = threadIdx.x;
    const float c0 = g_cst[0], c1 = g_cst[1], c2 = g_cst[2];
    size_t row = (size_t)blockIdx.x * 256 + tid;
    float4 p0 = g_part[row];
    float4 p1 = g_part[NROWS + row];
    float inv = 1.0f / (p0.x + p1.x);
    out[row*3 + 0] = fmaf(p0.y + p1.y, inv, c0);
    out[row*3 + 1] = fmaf(p0.z + p1.z, inv, c1);
    out[row*3 + 2] = fmaf(p0.w + p1.w, inv, c2);
}

extern "C" void kernel_launch(void* const* d_in, const int* in_sizes, int n_in,
                              void* d_out, int out_size) {
    const float* qin = (const float*)d_in[0];
    const float* kin = (const float*)d_in[1];
    const float* vin = (const float*)d_in[2];
    const float* Wq  = (const float*)d_in[3];
    const float* bq  = (const float*)d_in[4];
    const float* Wk  = (const float*)d_in[5];
    const float* bk  = (const float*)d_in[6];
    const float* Wv  = (const float*)d_in[7];
    const float* bv  = (const float*)d_in[8];
    const float* Wo  = (const float*)d_in[9];
    const float* bo  = (const float*)d_in[10];
    float* out = (float*)d_out;

    cudaFuncSetAttribute(flash12_kernel,
                         cudaFuncAttributeMaxDynamicSharedMemorySize, SMEM_BYTES);
    cudaFuncSetAttribute(proj7_kernel,
                         cudaFuncAttributeMaxDynamicSharedMemorySize, P7_SMEM);
    prep_kernel<<<34, 256>>>(Wq, Wk, Wv, Wo, bv, bo);
    proj7_kernel<<<512, 256, P7_SMEM>>>(qin, kin, vin, bq, bk);
    flash12_kernel<<<dim3(SS/128, BB, 2), 256, SMEM_BYTES>>>();
    finalize_kernel<<<NROWS/256, 256>>>(out);
}

// round 17
// speedup vs baseline: 1.7826x; 1.4866x over previous
#include <cuda_runtime.h>
#include <cuda_bf16.h>
#include <cuda_fp16.h>
#include <math.h>
#include <cstdint>

#define BB 32
#define SS 2048
#define FF 128
#define DK 32
#define NROWS (BB*SS)
#define SHIFT 4.0f     // softmax log2-domain shift (cancels in normalization)

// Packed projections, 32 fp16 per row (64B).
// q pre-scaled by log2(e)/sqrt(32)  (scores in log2 domain -> ex2)
__device__ __half g_qp[NROWS*32];
__device__ __half g_kp[NROWS*32];
// PV B-operand, pre-packed fp16x2: per key-pair p, 8 cols g:
//   g<3: {lo=vw[2p][g], hi=vw[2p+1][g]}, g==3: {1,1}, g>3: 0
__device__ uint32_t g_vwp[(NROWS/2)*8];
__device__ float4 g_part[2*NROWS];         // split-K partials {l, A0, A1, A2}
// Pre-split W images (ldmatrix-ready): per phase 8704 bf16 = 4352 hi + 4352 lo,
// layout img[c*136 + f] (c = out col 0..31, f = 0..127, 8 pad per row)
__device__ __nv_bfloat16 g_wimg[2][8704];
__device__ float g_wveff[FF*3];            // Wv @ Wo_eff
__device__ float g_cst[3];                 // bo + bv . Wo_eff

static __device__ __forceinline__ uint32_t smem_u32(const void* p) {
    uint32_t a;
    asm("{ .reg .u64 t; cvta.to.shared.u64 t, %1; cvt.u32.u64 %0, t; }" : "=r"(a) : "l"(p));
    return a;
}
static __device__ __forceinline__ void cp16(uint32_t dst, const void* src) {
    asm volatile("cp.async.cg.shared.global [%0], [%1], 16;" :: "r"(dst), "l"(src) : "memory");
}
#define CP_COMMIT() asm volatile("cp.async.commit_group;" ::: "memory")
#define CP_WAIT(n)  asm volatile("cp.async.wait_group %0;" :: "n"(n) : "memory")

// pack {lo, hi} floats -> bf16x2
static __device__ __forceinline__ uint32_t pkbf(float lo, float hi) {
    uint32_t r;
    asm("cvt.rn.bf16x2.f32 %0, %1, %2;" : "=r"(r) : "f"(hi), "f"(lo));
    return r;
}
// pack {lo, hi} floats -> f16x2
static __device__ __forceinline__ uint32_t pkhf(float lo, float hi) {
    uint32_t r;
    asm("cvt.rn.f16x2.f32 %0, %1, %2;" : "=r"(r) : "f"(hi), "f"(lo));
    return r;
}
// packed fp16x2 exp2
static __device__ __forceinline__ uint32_t ex2h2(uint32_t x) {
    uint32_t y;
    asm("ex2.approx.f16x2 %0, %1;" : "=r"(y) : "r"(x));
    return y;
}
// split a float2 into bf16x2 hi + bf16x2 lo words
static __device__ __forceinline__ void split2(float2 x, uint32_t& h, uint32_t& l) {
    h = pkbf(x.x, x.y);
    float f0 = __uint_as_float(h << 16);
    float f1 = __uint_as_float(h & 0xFFFF0000u);
    l = pkbf(x.x - f0, x.y - f1);
}

#define LDSM_X4(r0,r1,r2,r3,addr) \
    asm volatile("ldmatrix.sync.aligned.m8n8.x4.shared.b16 {%0,%1,%2,%3}, [%4];" \
        : "=r"(r0), "=r"(r1), "=r"(r2), "=r"(r3) : "r"(addr))

#define MMA16816(c0,c1,c2,c3,a0,a1,a2,a3,b0,b1) \
    asm volatile("mma.sync.aligned.m16n8k16.row.col.f32.bf16.bf16.f32 " \
        "{%0,%1,%2,%3}, {%4,%5,%6,%7}, {%8,%9}, {%0,%1,%2,%3};" \
        : "+f"(c0), "+f"(c1), "+f"(c2), "+f"(c3) \
        : "r"(a0), "r"(a1), "r"(a2), "r"(a3), "r"(b0), "r"(b1))

#define MMA16816H(c0,c1,c2,c3,a0,a1,a2,a3,b0,b1) \
    asm volatile("mma.sync.aligned.m16n8k16.row.col.f32.f16.f16.f32 " \
        "{%0,%1,%2,%3}, {%4,%5,%6,%7}, {%8,%9}, {%0,%1,%2,%3};" \
        : "+f"(c0), "+f"(c1), "+f"(c2), "+f"(c3) \
        : "r"(a0), "r"(a1), "r"(a2), "r"(a3), "r"(b0), "r"(b1))

// ---------------------------------------------------------------------------
// Prep: grid 34. Blocks 0-31: one W-image column each (both phases).
// Block 32: Wv_eff. Block 33: output constant.
// ---------------------------------------------------------------------------
__global__ __launch_bounds__(256) void prep_kernel(
    const float* __restrict__ Wq, const float* __restrict__ Wk,
    const float* __restrict__ Wv, const float* __restrict__ Wo,
    const float* __restrict__ bv, const float* __restrict__ bo) {
    __shared__ float sWoE[DK*3];
    const int tid = threadIdx.x;
    const int b = blockIdx.x;
    if (b < 32) {
        int c = b;
        int ph = tid >> 7;         // 0 or 1
        int f  = tid & 127;
        const float* W = ph ? Wk : Wq;
        __nv_bfloat16* img = g_wimg[ph];
        float w = W[f*32 + c];
        __nv_bfloat16 h = __float2bfloat16(w);
        img[c*136 + f]        = h;
        img[4352 + c*136 + f] = __float2bfloat16(w - __bfloat162float(h));
    } else if (b == 32) {
        if (tid < 96) {
            int d = tid / 3, f = tid - d*3;
            float s = 0.f;
            #pragma unroll
            for (int h = 0; h < 16; ++h) s += Wo[(h*DK + d)*3 + f];
            sWoE[tid] = s;
        }
        __syncthreads();
        for (int i = tid; i < FF*3; i += 256) {
            int r = i / 3, f = i - r*3;
            float s = 0.f;
            #pragma unroll
            for (int d = 0; d < DK; ++d) s = fmaf(Wv[r*DK + d], sWoE[d*3 + f], s);
            g_wveff[i] = s;
        }
    } else {
        if (tid < 3) {
            float s = bo[tid];
            #pragma unroll
            for (int d = 0; d < DK; ++d) {
                float w = 0.f;
                #pragma unroll
                for (int h = 0; h < 16; ++h) w += Wo[(h*DK + d)*3 + tid];
                s = fmaf(bv[d], w, s);
            }
            g_cst[tid] = s;
        }
    }
}

// ---------------------------------------------------------------------------
// Projection (merged): grid 512, 256 threads, 128 rows/block, ALL phases
// (Q, K, V) in one block. GEMM inputs use bf16 split (full precision);
// Q/K outputs are plain fp16 rows (64B).
// ---------------------------------------------------------------------------
#define P7_WQ 0
#define P7_WK 17408
#define P7_WV 34816                     // Wv_eff: 384 floats
#define P7_VS 36352                     // vw staging: 128*4 floats
#define P7_SMEM 38400

__global__ __launch_bounds__(256, 4) void proj7_kernel(
    const float* __restrict__ qin, const float* __restrict__ kin, const float* __restrict__ vin,
    const float* __restrict__ bq, const float* __restrict__ bk) {
    extern __shared__ __align__(16) unsigned char dsm[];
    const int tid  = threadIdx.x;
    const int wid  = tid >> 5, lane = tid & 31;
    const size_t row0 = (size_t)blockIdx.x * 128;
    const uint32_t sb = smem_u32(dsm);

    // stage both W images (34816 B) + Wv_eff (1536 B)
    for (int i = tid; i < 2176; i += 256)
        cp16(sb + i*16, (const unsigned char*)g_wimg[0] + i*16);
    for (int i = tid; i < 96; i += 256)
        cp16(sb + P7_WV + i*16, (const unsigned char*)g_wveff + i*16);
    CP_COMMIT();
    CP_WAIT(0);
    __syncthreads();

    const int gq = lane >> 2, tq = lane & 3;
    const int lr = lane & 7, sel = lane >> 3;

    // ---------------- Q and K phases ----------------
    #pragma unroll 1
    for (int phase = 0; phase < 2; ++phase) {
        const float* in = phase ? kin : qin;
        const float* bb = phase ? bk : bq;
        __half* gout = phase ? g_kp : g_qp;
        const float qs = phase ? 1.0f
                               : 0.17677669529663687f * 1.4426950408889634f;
        const uint32_t wbase = sb + phase*17408;

        const float* rp0 = in + (row0 + wid*16 + gq)*128;
        const float* rp1 = rp0 + 8*128;

        float acc[4][4];
        #pragma unroll
        for (int nt = 0; nt < 4; ++nt)
            #pragma unroll
            for (int i = 0; i < 4; ++i) acc[nt][i] = 0.f;

        #pragma unroll
        for (int g2 = 0; g2 < 4; ++g2) {
            uint32_t ah[2][4], al[2][4];
            #pragma unroll
            for (int gg = 0; gg < 2; ++gg) {
                int cb = (2*g2 + gg)*16 + tq*2;
                float2 x00 = *(const float2*)(rp0 + cb);
                float2 x10 = *(const float2*)(rp1 + cb);
                float2 x01 = *(const float2*)(rp0 + cb + 8);
                float2 x11 = *(const float2*)(rp1 + cb + 8);
                split2(x00, ah[gg][0], al[gg][0]);
                split2(x10, ah[gg][1], al[gg][1]);
                split2(x01, ah[gg][2], al[gg][2]);
                split2(x11, ah[gg][3], al[gg][3]);
            }
            #pragma unroll
            for (int nt = 0; nt < 4; ++nt) {
                uint32_t bwh = wbase + (nt*8 + lr)*272 + sel*16 + g2*64;
                uint32_t bwl = bwh + 8704;
                uint32_t bh[4], bl[4];
                LDSM_X4(bh[0], bh[1], bh[2], bh[3], bwh);
                LDSM_X4(bl[0], bl[1], bl[2], bl[3], bwl);
                MMA16816(acc[nt][0],acc[nt][1],acc[nt][2],acc[nt][3],
                         ah[0][0],ah[0][1],ah[0][2],ah[0][3], bh[0],bh[1]); // xh.wh
                MMA16816(acc[nt][0],acc[nt][1],acc[nt][2],acc[nt][3],
                         ah[1][0],ah[1][1],ah[1][2],ah[1][3], bh[2],bh[3]);
                MMA16816(acc[nt][0],acc[nt][1],acc[nt][2],acc[nt][3],
                         ah[0][0],ah[0][1],ah[0][2],ah[0][3], bl[0],bl[1]); // xh.wl
                MMA16816(acc[nt][0],acc[nt][1],acc[nt][2],acc[nt][3],
                         ah[1][0],ah[1][1],ah[1][2],ah[1][3], bl[2],bl[3]);
                MMA16816(acc[nt][0],acc[nt][1],acc[nt][2],acc[nt][3],
                         al[0][0],al[0][1],al[0][2],al[0][3], bh[0],bh[1]); // xl.wh
                MMA16816(acc[nt][0],acc[nt][1],acc[nt][2],acc[nt][3],
                         al[1][0],al[1][1],al[1][2],al[1][3], bh[2],bh[3]);
            }
        }

        // epilogue: bias + scale, packed fp16 stores (64B rows)
        #pragma unroll
        for (int nt = 0; nt < 4; ++nt) {
            int colp = nt*8 + tq*2;
            float b0 = bb[colp], b1 = bb[colp+1];
            #pragma unroll
            for (int hf = 0; hf < 2; ++hf) {
                size_t rrow = row0 + wid*16 + gq + hf*8;
                float v0 = (acc[nt][hf*2+0] + b0) * qs;
                float v1 = (acc[nt][hf*2+1] + b1) * qs;
                *(uint32_t*)((unsigned char*)gout + rrow*64 + colp*2) = pkhf(v0, v1);
            }
        }
    }

    // ---------------- V phase ----------------
    {
        float* sWv = (float*)(dsm + P7_WV);
        float* sVS = (float*)(dsm + P7_VS);
        #pragma unroll
        for (int it = 0; it < 2; ++it) {
            int r = it*64 + (tid >> 2);
            const float* rp = vin + (row0 + r)*128 + (tid & 3)*32;
            float a0 = 0.f, a1 = 0.f, a2 = 0.f;
            #pragma unroll
            for (int f4 = 0; f4 < 8; ++f4) {
                float4 x = ((const float4*)rp)[f4];
                int f = (tid & 3)*32 + f4*4;
                a0 = fmaf(x.x, sWv[(f+0)*3+0], a0); a1 = fmaf(x.x, sWv[(f+0)*3+1], a1); a2 = fmaf(x.x, sWv[(f+0)*3+2], a2);
                a0 = fmaf(x.y, sWv[(f+1)*3+0], a0); a1 = fmaf(x.y, sWv[(f+1)*3+1], a1); a2 = fmaf(x.y, sWv[(f+1)*3+2], a2);
                a0 = fmaf(x.z, sWv[(f+2)*3+0], a0); a1 = fmaf(x.z, sWv[(f+2)*3+1], a1); a2 = fmaf(x.z, sWv[(f+2)*3+2], a2);
                a0 = fmaf(x.w, sWv[(f+3)*3+0], a0); a1 = fmaf(x.w, sWv[(f+3)*3+1], a1); a2 = fmaf(x.w, sWv[(f+3)*3+2], a2);
            }
            a0 += __shfl_xor_sync(0xffffffffu, a0, 1); a0 += __shfl_xor_sync(0xffffffffu, a0, 2);
            a1 += __shfl_xor_sync(0xffffffffu, a1, 1); a1 += __shfl_xor_sync(0xffffffffu, a1, 2);
            a2 += __shfl_xor_sync(0xffffffffu, a2, 1); a2 += __shfl_xor_sync(0xffffffffu, a2, 2);
            if ((tid & 3) == 0) {
                sVS[r*4 + 0] = a0; sVS[r*4 + 1] = a1; sVS[r*4 + 2] = a2;
            }
        }
        __syncthreads();
        for (int i = tid; i < 512; i += 256) {
            int p = i >> 3, g = i & 7;
            uint32_t w;
            if (g < 3)       w = pkhf(sVS[(2*p)*4 + g], sVS[(2*p+1)*4 + g]);
            else if (g == 3) w = 0x3C003C00u;       // {1.0h, 1.0h}
            else             w = 0u;
            g_vwp[(row0 >> 1)*8 + i] = w;
        }
    }
}

// ---------------------------------------------------------------------------
// Flash kernel: 256 threads (8 warps x 16 q-rows), q-tile 128, split-K 2-way.
// fp16 single-term QK^T (4 MMAs per 16x16 tile); K rows 64B, smem stride 80B
// (conflict-free LDSM). Softmax via packed ex2.f16x2 (shift -SHIFT); PV via
// fp16 HMMA with packed vwp. smem 24.6 KB.
// ---------------------------------------------------------------------------
#define RSTRK 80
#define KTILEB (128*RSTRK)                 // 10240
#define RINGSTRIDE (KTILEB + 2048)         // 12288 (K tile + vwp)
#define SMEM_BYTES (2*RINGSTRIDE)          // 24576

__global__ __launch_bounds__(256, 4)
void flash13_kernel(void) {
    extern __shared__ __align__(16) unsigned char smem[];
    const int tid  = threadIdx.x;
    const int wid  = tid >> 5, lane = tid & 31;
    const size_t base = (size_t)blockIdx.y * SS;
    const int q0 = blockIdx.x * 128;
    const int z  = blockIdx.z;
    const uint32_t sbase = smem_u32(smem);

    // stage Q tile (128 rows x 64B = 8 KB) in ring buffer 1
    #pragma unroll
    for (int k = 0; k < 2; ++k) {
        int i = tid + k*256;
        cp16(sbase + RINGSTRIDE + i*16,
             (const unsigned char*)g_qp + (base + q0)*64 + i*16);
    }
    CP_COMMIT();
    // concurrently prefetch K tile 0 + vwp into ring buffer 0
    {
        const size_t kb = base + (size_t)z * 1024;
        #pragma unroll
        for (int k = 0; k < 2; ++k) {
            int i = tid + k*256;
            int rr = i >> 2, sg = i & 3;
            cp16(sbase + rr*RSTRK + sg*16,
                 (const unsigned char*)g_kp + (kb + rr)*64 + sg*16);
        }
        if (tid < 128)
            cp16(sbase + KTILEB + tid*16, g_vwp + (kb >> 1)*8 + tid*4);
    }
    CP_COMMIT();
    CP_WAIT(1);   // Q ready (K0 may still be in flight)
    __syncthreads();

    const int lr  = lane & 7;
    const int sel = lane >> 3;

    // A fragments (loop-invariant): k-steps {0,1} (one-time LDSM, minor
    // conflicts at stride 64 are acceptable)
    uint32_t aF[2][4];
    {
        int arow = wid*16 + lr + (sel & 1)*8;
        uint32_t abase = sbase + RINGSTRIDE + arow*64 + (sel >> 1)*16;
        #pragma unroll
        for (int g = 0; g < 2; ++g)
            LDSM_X4(aF[g][0], aF[g][1], aF[g][2], aF[g][3], abase + g*32);
    }
    __syncthreads();   // all warps done reading Q region (buffer 1)

    // PV accumulators: cols 2t,2t+1 (t=lane&3): t=0 -> {A0,A1}, t=1 -> {A2,l}
    float d[4] = {0.f, 0.f, 0.f, 0.f};
    const int tq = lane & 3, gq = lane >> 2;

    #pragma unroll 1
    for (int ti = 0; ti < 8; ++ti) {
        if (ti < 7) {
            const size_t kb = base + (size_t)z*1024 + (size_t)(ti+1)*128;
            uint32_t db = sbase + ((ti+1) & 1)*RINGSTRIDE;
            #pragma unroll
            for (int k = 0; k < 2; ++k) {
                int i = tid + k*256;
                int rr = i >> 2, sg = i & 3;
                cp16(db + rr*RSTRK + sg*16,
                     (const unsigned char*)g_kp + (kb + rr)*64 + sg*16);
            }
            if (tid < 128)
                cp16(db + KTILEB + tid*16, g_vwp + (kb >> 1)*8 + tid*4);
            CP_COMMIT();
            CP_WAIT(1);
        } else {
            CP_WAIT(0);
        }
        __syncthreads();

        const uint32_t sk  = sbase + (ti & 1)*RINGSTRIDE;
        const uint32_t svw = sk + KTILEB;

        #pragma unroll 4
        for (int jp = 0; jp < 8; ++jp) {
            uint32_t be[4], bo_[4];
            LDSM_X4(be[0],  be[1],  be[2],  be[3],
                    sk + ((2*jp)*8 + lr)*RSTRK + sel*16);
            LDSM_X4(bo_[0], bo_[1], bo_[2], bo_[3],
                    sk + ((2*jp+1)*8 + lr)*RSTRK + sel*16);
            uint32_t pb0, pb1;
            asm volatile("ld.shared.b32 %0, [%1];" : "=r"(pb0)
                         : "r"(svw + ((jp*8 + tq)*8 + gq)*4));
            asm volatile("ld.shared.b32 %0, [%1];" : "=r"(pb1)
                         : "r"(svw + ((jp*8 + 4 + tq)*8 + gq)*4));

            // single-term fp16 QK (q-row-common rounding cancels in softmax)
            float e0=-SHIFT,e1=-SHIFT,e2=-SHIFT,e3=-SHIFT;  // even n-tile
            float o0=0.f,o1=0.f,o2=0.f,o3=0.f;              // odd n-tile
            MMA16816H(e0,e1,e2,e3, aF[0][0],aF[0][1],aF[0][2],aF[0][3], be[0],be[1]);
            MMA16816H(o0,o1,o2,o3, aF[0][0],aF[0][1],aF[0][2],aF[0][3], bo_[0],bo_[1]);
            MMA16816H(e0,e1,e2,e3, aF[1][0],aF[1][1],aF[1][2],aF[1][3], be[2],be[3]);
            MMA16816H(o0,o1,o2,o3, aF[1][0],aF[1][1],aF[1][2],aF[1][3], bo_[2],bo_[3]);

            uint32_t a0 = ex2h2(pkhf(e0, e1));
            uint32_t a1 = ex2h2(pkhf(e2, e3));
            uint32_t a2 = ex2h2(pkhf(o0 - SHIFT, o1 - SHIFT));
            uint32_t a3 = ex2h2(pkhf(o2 - SHIFT, o3 - SHIFT));
            MMA16816H(d[0], d[1], d[2], d[3], a0, a1, a2, a3, pb0, pb1);
        }
        __syncthreads();
    }

    // gather: t=0 lanes hold {A0,A1}; t=1 lanes hold {A2,l}; shuffle-combine
    {
        float az_r0 = __shfl_xor_sync(0xffffffffu, d[0], 1);  // from t^1
        float l_r0  = __shfl_xor_sync(0xffffffffu, d[1], 1);
        float az_r1 = __shfl_xor_sync(0xffffffffu, d[2], 1);
        float l_r1  = __shfl_xor_sync(0xffffffffu, d[3], 1);
        if (tq == 0) {
            size_t r = base + q0 + wid*16 + gq;
            g_part[(size_t)z*NROWS + r]     = make_float4(l_r0, d[0], d[1], az_r0);
            g_part[(size_t)z*NROWS + r + 8] = make_float4(l_r1, d[2], d[3], az_r1);
        }
    }
}

// ---------------------------------------------------------------------------
// Finalize: combine 2 split-K partials, normalize, add precomputed constant.
// ---------------------------------------------------------------------------
__global__ __launch_bounds__(256) void finalize_kernel(float* __restrict__ out) {
    const int tid = threadIdx.x;
    const float c0 = g_cst[0], c1 = g_cst[1], c2 = g_cst[2];
    size_t row = (size_t)blockIdx.x * 256 + tid;
    float4 p0 = g_part[row];
    float4 p1 = g_part[NROWS + row];
    float inv = 1.0f / (p0.x + p1.x);
    out[row*3 + 0] = fmaf(p0.y + p1.y, inv, c0);
    out[row*3 + 1] = fmaf(p0.z + p1.z, inv, c1);
    out[row*3 + 2] = fmaf(p0.w + p1.w, inv, c2);
}

extern "C" void kernel_launch(void* const* d_in, const int* in_sizes, int n_in,
                              void* d_out, int out_size) {
    const float* qin = (const float*)d_in[0];
    const float* kin = (const float*)d_in[1];
    const float* vin = (const float*)d_in[2];
    const float* Wq  = (const float*)d_in[3];
    const float* bq  = (const float*)d_in[4];
    const float* Wk  = (const float*)d_in[5];
    const float* bk  = (const float*)d_in[6];
    const float* Wv  = (const float*)d_in[7];
    const float* bv  = (const float*)d_in[8];
    const float* Wo  = (const float*)d_in[9];
    const float* bo  = (const float*)d_in[10];
    float* out = (float*)d_out;

    cudaFuncSetAttribute(flash13_kernel,
                         cudaFuncAttributeMaxDynamicSharedMemorySize, SMEM_BYTES);
    cudaFuncSetAttribute(proj7_kernel,
                         cudaFuncAttributeMaxDynamicSharedMemorySize, P7_SMEM);
    prep_kernel<<<34, 256>>>(Wq, Wk, Wv, Wo, bv, bo);
    proj7_kernel<<<512, 256, P7_SMEM>>>(qin, kin, vin, bq, bk);
    flash13_kernel<<<dim3(SS/128, BB, 2), 256, SMEM_BYTES>>>();
    finalize_kernel<<<NROWS/256, 256>>>(out);
}